// round 3
// baseline (speedup 1.0000x reference)
#include <cuda_runtime.h>
#include <cstdint>
#include <cstddef>

#define N_NODES 100000
#define T_SEQ   1024
#define IN_CH   128
#define HID     256
#define G3      768     // 3*HID gate rows

// ---------------- scratch (device globals; no allocations allowed) ----------
#define K1_NCHUNK 37
#define K1_CHUNK  2720  // 85*32, 37*2720 = 100640 >= 100000 (guarded)

__device__ float g_part[K1_NCHUNK * T_SEQ * IN_CH];  // ~19.4 MB partials
__device__ float g_ve[T_SEQ * IN_CH];                // visit_emb [1024,128]
__device__ float g_gx[T_SEQ * G3];                   // input gates [1024,768]
__device__ float g_hs[T_SEQ * HID];                  // hidden states [1024,256]

// ============================================================================
// K1: part[c][t][i] = sum_{n in chunk c} H[n][t] * X[n][i]
// fp32 math via packed fma.rn.f32x2 (FFMA2): 2 FMAs per fma-pipe issue slot.
// ============================================================================
__global__ void __launch_bounds__(256, 2) k1_kernel(const float* __restrict__ H,
                                                    const float* __restrict__ X) {
    __shared__ __align__(16) float Hs[32][128];
    __shared__ __align__(16) float Xs[32][128];
    const int tid = threadIdx.x;
    const int tx = tid & 15, ty = tid >> 4;
    const int t0 = blockIdx.x * 128;
    const int n0 = blockIdx.y * K1_CHUNK;

    unsigned long long acc2[8][4];   // acc2[i][j] = (acc[i][2j], acc[i][2j+1])
#pragma unroll
    for (int i = 0; i < 8; i++)
#pragma unroll
        for (int j = 0; j < 4; j++) acc2[i][j] = 0ull;

    for (int nb = 0; nb < K1_CHUNK; nb += 32) {
#pragma unroll
        for (int v = 0; v < 4; v++) {
            int e = tid + v * 256;        // 0..1023 float4 slots
            int row = e >> 5;             // 0..31
            int c = (e & 31) << 2;        // 0..124 step 4
            int n = n0 + nb + row;
            float4 hv = make_float4(0.f, 0.f, 0.f, 0.f);
            float4 xv = make_float4(0.f, 0.f, 0.f, 0.f);
            if (n < N_NODES) {
                hv = *(const float4*)(H + (size_t)n * T_SEQ + t0 + c);
                xv = *(const float4*)(X + (size_t)n * IN_CH + c);
            }
            *(float4*)&Hs[row][c] = hv;
            *(float4*)&Xs[row][c] = xv;
        }
        __syncthreads();
#pragma unroll
        for (int kk = 0; kk < 32; kk++) {
            float a[8];
            *(float4*)&a[0] = *(const float4*)&Hs[kk][ty * 8];
            *(float4*)&a[4] = *(const float4*)&Hs[kk][ty * 8 + 4];
            unsigned long long bb[4];    // pair-packed B operands, free from SMEM
            *(ulonglong2*)&bb[0] = *(const ulonglong2*)&Xs[kk][tx * 8];
            *(ulonglong2*)&bb[2] = *(const ulonglong2*)&Xs[kk][tx * 8 + 4];
#pragma unroll
            for (int i = 0; i < 8; i++) {
                unsigned long long aa;
                unsigned int ai = __float_as_uint(a[i]);
                asm("mov.b64 %0, {%1, %1};" : "=l"(aa) : "r"(ai));
#pragma unroll
                for (int j = 0; j < 4; j++)
                    asm("fma.rn.f32x2 %0, %1, %2, %0;"
                        : "+l"(acc2[i][j]) : "l"(aa), "l"(bb[j]));
            }
        }
        __syncthreads();
    }

    float* pp = g_part + (size_t)blockIdx.y * (T_SEQ * IN_CH);
#pragma unroll
    for (int i = 0; i < 8; i++) {
        int t = t0 + ty * 8 + i;
        *(ulonglong2*)&pp[t * IN_CH + tx * 8] =
            make_ulonglong2(acc2[i][0], acc2[i][1]);
        *(ulonglong2*)&pp[t * IN_CH + tx * 8 + 4] =
            make_ulonglong2(acc2[i][2], acc2[i][3]);
    }
}

// K1b: ve = sum over 37 chunk partials (deterministic reduce)
__global__ void __launch_bounds__(256) k1_reduce_kernel() {
    int idx = blockIdx.x * blockDim.x + threadIdx.x;   // 0..131071
    float s = 0.f;
#pragma unroll
    for (int c = 0; c < K1_NCHUNK; c++) s += g_part[c * (T_SEQ * IN_CH) + idx];
    g_ve[idx] = s;
}

// ============================================================================
// K2: gx[t][r] = b_ih[r] + sum_k ve[t][k]*w_ih[r][k]
// ============================================================================
__global__ void __launch_bounds__(256) gx_kernel(const float* __restrict__ w_ih,
                                                 const float* __restrict__ b_ih) {
    const int t = blockIdx.x;
    const int w = threadIdx.x >> 5, l = threadIdx.x & 31;
    float4 vv = *(const float4*)(g_ve + t * IN_CH + l * 4);
    for (int rr = 0; rr < 96; rr++) {
        int r = w * 96 + rr;
        float4 wv = *(const float4*)(w_ih + (size_t)r * IN_CH + l * 4);
        float p = vv.x * wv.x + vv.y * wv.y + vv.z * wv.z + vv.w * wv.w;
#pragma unroll
        for (int o = 16; o; o >>= 1) p += __shfl_xor_sync(0xffffffffu, p, o);
        if (l == 0) g_gx[t * G3 + r] = p + b_ih[r];
    }
}

// ============================================================================
// K3: sequential GRU, cluster of 8 CTAs x 384 threads.
// Weights register-resident (64 fp32/thread; 4-way k-split x 96 rows/CTA).
// Per-step handshake via full/empty mbarriers + DSMEM h broadcast.
// ============================================================================
__device__ __forceinline__ void cluster_sync_() {
    asm volatile("barrier.cluster.arrive.aligned;" ::: "memory");
    asm volatile("barrier.cluster.wait.aligned;" ::: "memory");
}
__device__ __forceinline__ void st_remote_f32(uint32_t laddr, uint32_t peer, float v) {
    uint32_t raddr;
    asm volatile("mapa.shared::cluster.u32 %0, %1, %2;"
                 : "=r"(raddr) : "r"(laddr), "r"(peer));
    asm volatile("st.shared::cluster.f32 [%0], %1;" :: "r"(raddr), "f"(v) : "memory");
}
__device__ __forceinline__ void arrive_remote(uint32_t lbar, uint32_t peer) {
    uint32_t raddr;
    asm volatile("mapa.shared::cluster.u32 %0, %1, %2;"
                 : "=r"(raddr) : "r"(lbar), "r"(peer));
    asm volatile("mbarrier.arrive.release.cluster.shared::cluster.b64 _, [%0];"
                 :: "r"(raddr) : "memory");
}
__device__ __forceinline__ void wait_parity_cl(uint32_t bar, uint32_t par) {
    uint32_t done;
    do {
        asm volatile(
            "{\n\t.reg .pred p;\n\t"
            "mbarrier.try_wait.parity.acquire.cluster.shared::cta.b64 p, [%1], %2, 0x989680;\n\t"
            "selp.b32 %0, 1, 0, p;\n\t}"
            : "=r"(done) : "r"(bar), "r"(par) : "memory");
    } while (!done);
}
__device__ __forceinline__ float sigmoid_f(float x) {
    return 1.f / (1.f + __expf(-x));
}
__device__ __forceinline__ float tanh_f(float x) {
    x = fminf(fmaxf(x, -15.f), 15.f);          // NaN-safe clamp (|x|>15 -> +-1)
    float e2 = __expf(-2.f * x);
    return (1.f - e2) / (1.f + e2);
}

#define GRU_STEP(T_, B_, PF_, PE_) do {                                        \
    const int nb_ = (B_) ^ 1;                                                  \
    float gxr = 0.f, gxz = 0.f, gxn = 0.f, hprev = 0.f;                        \
    if (tid < 32) {                                                            \
        const float* gxt = g_gx + (T_) * G3 + rank * 32 + tid;                 \
        gxr = gxt[0]; gxz = gxt[256]; gxn = gxt[512];                          \
    }                                                                          \
    if ((T_) > 0) { wait_parity_cl(bar_full[(B_)], PF_); PF_ ^= 1u; }          \
    if (tid < 32) hprev = sh_h[(B_)][rank * 32 + tid];                         \
    {                                                                          \
        const float4* hp4 = (const float4*)&sh_h[(B_)][q * 64];                \
        float a0 = 0.f, a1 = 0.f, a2 = 0.f, a3 = 0.f;                          \
        _Pragma("unroll")                                                      \
        for (int j = 0; j < 16; j++) {                                         \
            float4 hv = hp4[j];                                                \
            a0 = fmaf(w[4 * j + 0], hv.x, a0);                                 \
            a1 = fmaf(w[4 * j + 1], hv.y, a1);                                 \
            a2 = fmaf(w[4 * j + 2], hv.z, a2);                                 \
            a3 = fmaf(w[4 * j + 3], hv.w, a3);                                 \
        }                                                                      \
        sh_part[q * 96 + lr] = (a0 + a1) + (a2 + a3);                          \
    }                                                                          \
    __syncthreads();                                                           \
    if (tid == 0 && (T_) < T_SEQ - 1) {                                        \
        _Pragma("unroll")                                                      \
        for (int p = 0; p < 8; p++) arrive_remote(bar_empty[(B_)], p);         \
    }                                                                          \
    if (tid < 32) {                                                            \
        float ghr = ((sh_part[tid] + sh_part[96 + tid]) +                      \
                     (sh_part[192 + tid] + sh_part[288 + tid])) + bh0;         \
        float ghz = ((sh_part[32 + tid] + sh_part[128 + tid]) +                \
                     (sh_part[224 + tid] + sh_part[320 + tid])) + bh1;         \
        float ghn = ((sh_part[64 + tid] + sh_part[160 + tid]) +                \
                     (sh_part[256 + tid] + sh_part[352 + tid])) + bh2;         \
        float r = sigmoid_f(gxr + ghr);                                        \
        float z = sigmoid_f(gxz + ghz);                                        \
        float n = tanh_f(gxn + r * ghn);                                       \
        float hnew = n + z * (hprev - n);                                      \
        g_hs[(T_) * HID + rank * 32 + tid] = hnew;                             \
        if ((T_) < T_SEQ - 1) {                                                \
            if ((T_) > 0) { wait_parity_cl(bar_empty[nb_], PE_); PE_ ^= 1u; }  \
            uint32_t laddr = (uint32_t)__cvta_generic_to_shared(               \
                &sh_h[nb_][rank * 32 + tid]);                                  \
            _Pragma("unroll")                                                  \
            for (int p = 0; p < 8; p++) st_remote_f32(laddr, p, hnew);         \
            _Pragma("unroll")                                                  \
            for (int p = 0; p < 8; p++) arrive_remote(bar_full[nb_], p);       \
        }                                                                      \
    }                                                                          \
} while (0)

__global__ __launch_bounds__(384, 1) __cluster_dims__(8, 1, 1)
void gru_kernel(const float* __restrict__ w_hh, const float* __restrict__ b_hh) {
    __shared__ __align__(16) float sh_h[2][256];   // double-buffered hidden state
    __shared__ float sh_part[384];                 // 4 k-quarters x 96 rows
    __shared__ __align__(8) unsigned long long sh_bar[4];  // full0,full1,empty0,empty1

    const int tid = threadIdx.x;
    const int rank = blockIdx.x;
    const int q = tid / 96;                 // k-quarter 0..3
    const int lr = tid - q * 96;            // local row 0..95
    const int grow = (lr >> 5) * 256 + rank * 32 + (lr & 31);

    // register-resident weights: w_hh[grow][q*64 .. q*64+63]
    float w[64];
    {
        const float* wp = w_hh + (size_t)grow * 256 + q * 64;
#pragma unroll
        for (int j = 0; j < 64; j++) w[j] = wp[j];
    }
    float bh0 = 0.f, bh1 = 0.f, bh2 = 0.f;
    if (tid < 32) {
        bh0 = b_hh[rank * 32 + tid];
        bh1 = b_hh[256 + rank * 32 + tid];
        bh2 = b_hh[512 + rank * 32 + tid];
    }
    if (tid < 256) sh_h[0][tid] = 0.f;      // h0 = 0

    uint32_t bbase = (uint32_t)__cvta_generic_to_shared(&sh_bar[0]);
    uint32_t bar_full[2]  = {bbase, bbase + 8};
    uint32_t bar_empty[2] = {bbase + 16, bbase + 24};
    if (tid == 0) {
        asm volatile("mbarrier.init.shared.b64 [%0], %1;" :: "r"(bar_full[0]),  "r"(256) : "memory");
        asm volatile("mbarrier.init.shared.b64 [%0], %1;" :: "r"(bar_full[1]),  "r"(256) : "memory");
        asm volatile("mbarrier.init.shared.b64 [%0], %1;" :: "r"(bar_empty[0]), "r"(8)   : "memory");
        asm volatile("mbarrier.init.shared.b64 [%0], %1;" :: "r"(bar_empty[1]), "r"(8)   : "memory");
    }
    __syncthreads();
    cluster_sync_();   // all barriers initialized cluster-wide

    uint32_t pf0 = 0, pf1 = 0, pe0 = 0, pe1 = 0;
    for (int t = 0; t < T_SEQ; t += 2) {
        GRU_STEP(t,     0, pf0, pe1);
        GRU_STEP(t + 1, 1, pf1, pe0);
    }
    cluster_sync_();
}

// ============================================================================
// K4: logits = hs @ w_attn; alpha = softmax(logits); out = alpha @ hs
// ============================================================================
__global__ void __launch_bounds__(1024) attn_kernel(const float* __restrict__ w_attn,
                                                    float* __restrict__ out) {
    __shared__ float s_alpha[1024];
    __shared__ float s_red[1024];
    __shared__ float s_wa[256];
    const int tid = threadIdx.x;
    if (tid < 256) s_wa[tid] = w_attn[tid];
    __syncthreads();

    const int w = tid >> 5, l = tid & 31;
    for (int tt = 0; tt < 32; tt++) {
        int t = w * 32 + tt;
        const float* hr = g_hs + t * HID;
        float p = 0.f;
#pragma unroll
        for (int j = 0; j < 8; j++) p = fmaf(hr[l + 32 * j], s_wa[l + 32 * j], p);
#pragma unroll
        for (int o = 16; o; o >>= 1) p += __shfl_xor_sync(0xffffffffu, p, o);
        if (l == 0) s_alpha[t] = p;
    }
    __syncthreads();

    float v = s_alpha[tid];
    s_red[tid] = v;
    __syncthreads();
    for (int s = 512; s; s >>= 1) {
        if (tid < s) s_red[tid] = fmaxf(s_red[tid], s_red[tid + s]);
        __syncthreads();
    }
    float m = s_red[0];
    __syncthreads();
    float e = __expf(v - m);
    s_red[tid] = e;
    __syncthreads();
    for (int s = 512; s; s >>= 1) {
        if (tid < s) s_red[tid] = s_red[tid] + s_red[tid + s];
        __syncthreads();
    }
    float inv = 1.f / s_red[0];
    __syncthreads();
    s_alpha[tid] = e * inv;
    __syncthreads();

    const int j = tid & 255, seg = tid >> 8;
    float p = 0.f;
    const float* hp = g_hs + (size_t)seg * 256 * HID + j;
    const float* ap = s_alpha + seg * 256;
    for (int t = 0; t < 256; t++) p = fmaf(ap[t], hp[t * HID], p);
    s_red[tid] = p;
    __syncthreads();
    if (tid < 256)
        out[j] = (s_red[j] + s_red[256 + j]) + (s_red[512 + j] + s_red[768 + j]);
}

// ============================================================================
extern "C" void kernel_launch(void* const* d_in, const int* in_sizes, int n_in,
                              void* d_out, int out_size) {
    const float* X = nullptr;
    const float* H = nullptr;
    const float* w_ih = nullptr;
    const float* w_hh = nullptr;
    const float* b_ih = nullptr;
    const float* b_hh = nullptr;
    const float* w_attn = nullptr;
    for (int i = 0; i < n_in; i++) {
        int s = in_sizes[i];
        const float* p = (const float*)d_in[i];
        if (s == N_NODES * IN_CH)      X = p;
        else if (s == N_NODES * T_SEQ) H = p;
        else if (s == G3 * IN_CH)      w_ih = p;
        else if (s == G3 * HID)        w_hh = p;
        else if (s == G3) { if (!b_ih) b_ih = p; else b_hh = p; }
        else if (s == HID)             w_attn = p;
    }
    float* out = (float*)d_out;

    k1_kernel<<<dim3(8, K1_NCHUNK), 256>>>(H, X);
    k1_reduce_kernel<<<(T_SEQ * IN_CH) / 256, 256>>>();
    gx_kernel<<<T_SEQ, 256>>>(w_ih, b_ih);
    gru_kernel<<<8, 384>>>(w_hh, b_hh);
    attn_kernel<<<1, 1024>>>(w_attn, out);
}

// round 4
// speedup vs baseline: 2.4737x; 2.4737x over previous
#include <cuda_runtime.h>
#include <cstdint>
#include <cstddef>

#define N_NODES 100000
#define T_SEQ   1024
#define IN_CH   128
#define HID     256
#define G3      768     // 3*HID gate rows

// ---------------- scratch (device globals; no allocations allowed) ----------
#define K1_NCHUNK 37
#define K1_CHUNK  2720  // 85*32, 37*2720 = 100640 >= 100000 (guarded)

__device__ float g_part[K1_NCHUNK * T_SEQ * IN_CH];  // ~19.4 MB partials
__device__ float g_ve[T_SEQ * IN_CH];                // visit_emb [1024,128]
__device__ float g_gx[T_SEQ * G3];                   // input gates [1024,768]
__device__ float g_hs[T_SEQ * HID];                  // hidden states [1024,256]

// ============================================================================
// K1: part[c][t][i] = sum_{n in chunk c} H[n][t] * X[n][i]
// fp32 math via packed fma.rn.f32x2 (FFMA2): 2 FMAs per fma-pipe issue slot.
// ============================================================================
__global__ void __launch_bounds__(256, 2) k1_kernel(const float* __restrict__ H,
                                                    const float* __restrict__ X) {
    __shared__ __align__(16) float Hs[32][128];
    __shared__ __align__(16) float Xs[32][128];
    const int tid = threadIdx.x;
    const int tx = tid & 15, ty = tid >> 4;
    const int t0 = blockIdx.x * 128;
    const int n0 = blockIdx.y * K1_CHUNK;

    unsigned long long acc2[8][4];   // acc2[i][j] = (acc[i][2j], acc[i][2j+1])
#pragma unroll
    for (int i = 0; i < 8; i++)
#pragma unroll
        for (int j = 0; j < 4; j++) acc2[i][j] = 0ull;

    for (int nb = 0; nb < K1_CHUNK; nb += 32) {
#pragma unroll
        for (int v = 0; v < 4; v++) {
            int e = tid + v * 256;        // 0..1023 float4 slots
            int row = e >> 5;             // 0..31
            int c = (e & 31) << 2;        // 0..124 step 4
            int n = n0 + nb + row;
            float4 hv = make_float4(0.f, 0.f, 0.f, 0.f);
            float4 xv = make_float4(0.f, 0.f, 0.f, 0.f);
            if (n < N_NODES) {
                hv = *(const float4*)(H + (size_t)n * T_SEQ + t0 + c);
                xv = *(const float4*)(X + (size_t)n * IN_CH + c);
            }
            *(float4*)&Hs[row][c] = hv;
            *(float4*)&Xs[row][c] = xv;
        }
        __syncthreads();
#pragma unroll
        for (int kk = 0; kk < 32; kk++) {
            float a[8];
            *(float4*)&a[0] = *(const float4*)&Hs[kk][ty * 8];
            *(float4*)&a[4] = *(const float4*)&Hs[kk][ty * 8 + 4];
            unsigned long long bb[4];    // pair-packed B operands, free from SMEM
            *(ulonglong2*)&bb[0] = *(const ulonglong2*)&Xs[kk][tx * 8];
            *(ulonglong2*)&bb[2] = *(const ulonglong2*)&Xs[kk][tx * 8 + 4];
#pragma unroll
            for (int i = 0; i < 8; i++) {
                unsigned long long aa;
                unsigned int ai = __float_as_uint(a[i]);
                asm("mov.b64 %0, {%1, %1};" : "=l"(aa) : "r"(ai));
#pragma unroll
                for (int j = 0; j < 4; j++)
                    asm("fma.rn.f32x2 %0, %1, %2, %0;"
                        : "+l"(acc2[i][j]) : "l"(aa), "l"(bb[j]));
            }
        }
        __syncthreads();
    }

    float* pp = g_part + (size_t)blockIdx.y * (T_SEQ * IN_CH);
#pragma unroll
    for (int i = 0; i < 8; i++) {
        int t = t0 + ty * 8 + i;
        *(ulonglong2*)&pp[t * IN_CH + tx * 8] =
            make_ulonglong2(acc2[i][0], acc2[i][1]);
        *(ulonglong2*)&pp[t * IN_CH + tx * 8 + 4] =
            make_ulonglong2(acc2[i][2], acc2[i][3]);
    }
}

// K1b: ve = sum over 37 chunk partials (deterministic reduce)
__global__ void __launch_bounds__(256) k1_reduce_kernel() {
    int idx = blockIdx.x * blockDim.x + threadIdx.x;   // 0..131071
    float s = 0.f;
#pragma unroll
    for (int c = 0; c < K1_NCHUNK; c++) s += g_part[c * (T_SEQ * IN_CH) + idx];
    g_ve[idx] = s;
}

// ============================================================================
// K2: gx[t][r] = b_ih[r] + sum_k ve[t][k]*w_ih[r][k]
// ============================================================================
__global__ void __launch_bounds__(256) gx_kernel(const float* __restrict__ w_ih,
                                                 const float* __restrict__ b_ih) {
    const int t = blockIdx.x;
    const int w = threadIdx.x >> 5, l = threadIdx.x & 31;
    float4 vv = *(const float4*)(g_ve + t * IN_CH + l * 4);
    for (int rr = 0; rr < 96; rr++) {
        int r = w * 96 + rr;
        float4 wv = *(const float4*)(w_ih + (size_t)r * IN_CH + l * 4);
        float p = vv.x * wv.x + vv.y * wv.y + vv.z * wv.z + vv.w * wv.w;
#pragma unroll
        for (int o = 16; o; o >>= 1) p += __shfl_xor_sync(0xffffffffu, p, o);
        if (l == 0) g_gx[t * G3 + r] = p + b_ih[r];
    }
}

// ============================================================================
// K3: sequential GRU, cluster of 8 CTAs x 384 threads.
// Weights register-resident as f32x2 pairs (32 ull/thread; 4-way k-split x
// 96 rows/CTA). Per-step handshake: DSMEM h broadcast + ONE cluster.sync
// (round-2-proven; round-3's per-step mbarrier mesh was 2.7us/step slower).
// ============================================================================
__device__ __forceinline__ void cluster_sync_() {
    asm volatile("barrier.cluster.arrive.aligned;" ::: "memory");
    asm volatile("barrier.cluster.wait.aligned;" ::: "memory");
}
__device__ __forceinline__ void st_remote_f32(uint32_t laddr, uint32_t peer, float v) {
    uint32_t raddr;
    asm volatile("mapa.shared::cluster.u32 %0, %1, %2;"
                 : "=r"(raddr) : "r"(laddr), "r"(peer));
    asm volatile("st.shared::cluster.f32 [%0], %1;" :: "r"(raddr), "f"(v) : "memory");
}
__device__ __forceinline__ float sigmoid_f(float x) {
    return 1.f / (1.f + __expf(-x));
}
__device__ __forceinline__ float tanh_f(float x) {
    x = fminf(fmaxf(x, -15.f), 15.f);          // NaN-safe clamp (|x|>15 -> +-1)
    float e2 = __expf(-2.f * x);
    return (1.f - e2) / (1.f + e2);
}

__global__ __launch_bounds__(384, 1) __cluster_dims__(8, 1, 1)
void gru_kernel(const float* __restrict__ w_hh, const float* __restrict__ b_hh) {
    __shared__ __align__(16) float sh_h[2][256];   // double-buffered hidden state
    __shared__ float sh_part[384];                 // 4 k-quarters x 96 rows

    const int tid = threadIdx.x;
    const int rank = blockIdx.x;
    const int q = tid / 96;                 // k-quarter 0..3 (warp-aligned: 96=3 warps)
    const int lr = tid - q * 96;            // local row 0..95
    const int grow = (lr >> 5) * 256 + rank * 32 + (lr & 31);

    // register-resident weights as f32x2 pairs: rows grow, k in [q*64, q*64+64)
    unsigned long long w2[32];
    {
        const ulonglong2* wp =
            (const ulonglong2*)(w_hh + (size_t)grow * 256 + q * 64);
#pragma unroll
        for (int j = 0; j < 16; j++) {
            ulonglong2 v = wp[j];
            w2[2 * j] = v.x;
            w2[2 * j + 1] = v.y;
        }
    }
    float bh0 = 0.f, bh1 = 0.f, bh2 = 0.f;
    if (tid < 32) {
        bh0 = b_hh[rank * 32 + tid];
        bh1 = b_hh[256 + rank * 32 + tid];
        bh2 = b_hh[512 + rank * 32 + tid];
    }
    if (tid < 256) { sh_h[0][tid] = 0.f; sh_h[1][tid] = 0.f; }
    __syncthreads();
    cluster_sync_();

    for (int t = 0; t < T_SEQ; t++) {
        const int cur = t & 1, nxt = cur ^ 1;

        // prefetch this step's input gates (consumed in epilogue)
        float gxr = 0.f, gxz = 0.f, gxn = 0.f, hprev = 0.f;
        if (tid < 32) {
            const float* gxt = g_gx + t * G3 + rank * 32 + tid;
            gxr = gxt[0]; gxz = gxt[256]; gxn = gxt[512];
            hprev = sh_h[cur][rank * 32 + tid];
        }

        // quarter-matvec: sum over k in [q*64, q*64+64), f32x2 packed
        {
            const ulonglong2* hp = (const ulonglong2*)&sh_h[cur][q * 64];
            unsigned long long acc[4] = {0ull, 0ull, 0ull, 0ull};
#pragma unroll
            for (int j = 0; j < 16; j++) {
                ulonglong2 hv = hp[j];
                asm("fma.rn.f32x2 %0, %1, %2, %0;"
                    : "+l"(acc[(2 * j) & 3]) : "l"(w2[2 * j]), "l"(hv.x));
                asm("fma.rn.f32x2 %0, %1, %2, %0;"
                    : "+l"(acc[(2 * j + 1) & 3]) : "l"(w2[2 * j + 1]), "l"(hv.y));
            }
            float s0, s1, s2, s3, s4, s5, s6, s7;
            asm("mov.b64 {%0, %1}, %2;" : "=f"(s0), "=f"(s1) : "l"(acc[0]));
            asm("mov.b64 {%0, %1}, %2;" : "=f"(s2), "=f"(s3) : "l"(acc[1]));
            asm("mov.b64 {%0, %1}, %2;" : "=f"(s4), "=f"(s5) : "l"(acc[2]));
            asm("mov.b64 {%0, %1}, %2;" : "=f"(s6), "=f"(s7) : "l"(acc[3]));
            sh_part[q * 96 + lr] = ((s0 + s1) + (s2 + s3)) + ((s4 + s5) + (s6 + s7));
        }
        __syncthreads();

        if (tid < 32) {
            float ghr = ((sh_part[tid] + sh_part[96 + tid]) +
                         (sh_part[192 + tid] + sh_part[288 + tid])) + bh0;
            float ghz = ((sh_part[32 + tid] + sh_part[128 + tid]) +
                         (sh_part[224 + tid] + sh_part[320 + tid])) + bh1;
            float ghn = ((sh_part[64 + tid] + sh_part[160 + tid]) +
                         (sh_part[256 + tid] + sh_part[352 + tid])) + bh2;
            float r = sigmoid_f(gxr + ghr);
            float z = sigmoid_f(gxz + ghz);
            float n = tanh_f(gxn + r * ghn);
            float hnew = n + z * (hprev - n);
            g_hs[t * HID + rank * 32 + tid] = hnew;
            // broadcast into every CTA's next-buffer h (incl. self)
            uint32_t laddr = (uint32_t)__cvta_generic_to_shared(
                &sh_h[nxt][rank * 32 + tid]);
#pragma unroll
            for (int p = 0; p < 8; p++) st_remote_f32(laddr, (uint32_t)p, hnew);
        }
        cluster_sync_();  // orders DSMEM stores before next step's reads
    }
}

// ============================================================================
// K4: logits = hs @ w_attn; alpha = softmax(logits); out = alpha @ hs
// ============================================================================
__global__ void __launch_bounds__(1024) attn_kernel(const float* __restrict__ w_attn,
                                                    float* __restrict__ out) {
    __shared__ float s_alpha[1024];
    __shared__ float s_red[1024];
    __shared__ float s_wa[256];
    const int tid = threadIdx.x;
    if (tid < 256) s_wa[tid] = w_attn[tid];
    __syncthreads();

    const int w = tid >> 5, l = tid & 31;
    for (int tt = 0; tt < 32; tt++) {
        int t = w * 32 + tt;
        const float* hr = g_hs + t * HID;
        float p = 0.f;
#pragma unroll
        for (int j = 0; j < 8; j++) p = fmaf(hr[l + 32 * j], s_wa[l + 32 * j], p);
#pragma unroll
        for (int o = 16; o; o >>= 1) p += __shfl_xor_sync(0xffffffffu, p, o);
        if (l == 0) s_alpha[t] = p;
    }
    __syncthreads();

    float v = s_alpha[tid];
    s_red[tid] = v;
    __syncthreads();
    for (int s = 512; s; s >>= 1) {
        if (tid < s) s_red[tid] = fmaxf(s_red[tid], s_red[tid + s]);
        __syncthreads();
    }
    float m = s_red[0];
    __syncthreads();
    float e = __expf(v - m);
    s_red[tid] = e;
    __syncthreads();
    for (int s = 512; s; s >>= 1) {
        if (tid < s) s_red[tid] = s_red[tid] + s_red[tid + s];
        __syncthreads();
    }
    float inv = 1.f / s_red[0];
    __syncthreads();
    s_alpha[tid] = e * inv;
    __syncthreads();

    const int j = tid & 255, seg = tid >> 8;
    float p = 0.f;
    const float* hp = g_hs + (size_t)seg * 256 * HID + j;
    const float* ap = s_alpha + seg * 256;
    for (int t = 0; t < 256; t++) p = fmaf(ap[t], hp[t * HID], p);
    s_red[tid] = p;
    __syncthreads();
    if (tid < 256)
        out[j] = (s_red[j] + s_red[256 + j]) + (s_red[512 + j] + s_red[768 + j]);
}

// ============================================================================
extern "C" void kernel_launch(void* const* d_in, const int* in_sizes, int n_in,
                              void* d_out, int out_size) {
    const float* X = nullptr;
    const float* H = nullptr;
    const float* w_ih = nullptr;
    const float* w_hh = nullptr;
    const float* b_ih = nullptr;
    const float* b_hh = nullptr;
    const float* w_attn = nullptr;
    for (int i = 0; i < n_in; i++) {
        int s = in_sizes[i];
        const float* p = (const float*)d_in[i];
        if (s == N_NODES * IN_CH)      X = p;
        else if (s == N_NODES * T_SEQ) H = p;
        else if (s == G3 * IN_CH)      w_ih = p;
        else if (s == G3 * HID)        w_hh = p;
        else if (s == G3) { if (!b_ih) b_ih = p; else b_hh = p; }
        else if (s == HID)             w_attn = p;
    }
    float* out = (float*)d_out;

    k1_kernel<<<dim3(8, K1_NCHUNK), 256>>>(H, X);
    k1_reduce_kernel<<<(T_SEQ * IN_CH) / 256, 256>>>();
    gx_kernel<<<T_SEQ, 256>>>(w_ih, b_ih);
    gru_kernel<<<8, 384>>>(w_hh, b_hh);
    attn_kernel<<<1, 1024>>>(w_attn, out);
}

// round 5
// speedup vs baseline: 2.8197x; 1.1399x over previous
#include <cuda_runtime.h>
#include <cstdint>
#include <cstddef>

#define N_NODES 100000
#define T_SEQ   1024
#define IN_CH   128
#define HID     256
#define G3      768     // 3*HID gate rows

// ---------------- scratch (device globals; no allocations allowed) ----------
#define K1_NCHUNK 37
#define K1_CHUNK  2720  // 85*32, 37*2720 = 100640 >= 100000 (guarded)

__device__ float g_part[K1_NCHUNK * T_SEQ * IN_CH];  // ~19.4 MB partials
__device__ float g_ve[T_SEQ * IN_CH];                // visit_emb [1024,128]
__device__ float g_gx[T_SEQ * G3];                   // input gates [1024,768]
__device__ float g_hs[T_SEQ * HID];                  // hidden states [1024,256]

// ============================================================================
// K1: part[c][t][i] = sum_{n in chunk c} H[n][t] * X[n][i]
// fp32 math via packed fma.rn.f32x2 (FFMA2): 2 FMAs per fma-pipe issue slot.
// ============================================================================
__global__ void __launch_bounds__(256, 2) k1_kernel(const float* __restrict__ H,
                                                    const float* __restrict__ X) {
    __shared__ __align__(16) float Hs[32][128];
    __shared__ __align__(16) float Xs[32][128];
    const int tid = threadIdx.x;
    const int tx = tid & 15, ty = tid >> 4;
    const int t0 = blockIdx.x * 128;
    const int n0 = blockIdx.y * K1_CHUNK;

    unsigned long long acc2[8][4];   // acc2[i][j] = (acc[i][2j], acc[i][2j+1])
#pragma unroll
    for (int i = 0; i < 8; i++)
#pragma unroll
        for (int j = 0; j < 4; j++) acc2[i][j] = 0ull;

    for (int nb = 0; nb < K1_CHUNK; nb += 32) {
#pragma unroll
        for (int v = 0; v < 4; v++) {
            int e = tid + v * 256;        // 0..1023 float4 slots
            int row = e >> 5;             // 0..31
            int c = (e & 31) << 2;        // 0..124 step 4
            int n = n0 + nb + row;
            float4 hv = make_float4(0.f, 0.f, 0.f, 0.f);
            float4 xv = make_float4(0.f, 0.f, 0.f, 0.f);
            if (n < N_NODES) {
                hv = *(const float4*)(H + (size_t)n * T_SEQ + t0 + c);
                xv = *(const float4*)(X + (size_t)n * IN_CH + c);
            }
            *(float4*)&Hs[row][c] = hv;
            *(float4*)&Xs[row][c] = xv;
        }
        __syncthreads();
#pragma unroll
        for (int kk = 0; kk < 32; kk++) {
            float a[8];
            *(float4*)&a[0] = *(const float4*)&Hs[kk][ty * 8];
            *(float4*)&a[4] = *(const float4*)&Hs[kk][ty * 8 + 4];
            unsigned long long bb[4];    // pair-packed B operands, free from SMEM
            *(ulonglong2*)&bb[0] = *(const ulonglong2*)&Xs[kk][tx * 8];
            *(ulonglong2*)&bb[2] = *(const ulonglong2*)&Xs[kk][tx * 8 + 4];
#pragma unroll
            for (int i = 0; i < 8; i++) {
                unsigned long long aa;
                unsigned int ai = __float_as_uint(a[i]);
                asm("mov.b64 %0, {%1, %1};" : "=l"(aa) : "r"(ai));
#pragma unroll
                for (int j = 0; j < 4; j++)
                    asm("fma.rn.f32x2 %0, %1, %2, %0;"
                        : "+l"(acc2[i][j]) : "l"(aa), "l"(bb[j]));
            }
        }
        __syncthreads();
    }

    float* pp = g_part + (size_t)blockIdx.y * (T_SEQ * IN_CH);
#pragma unroll
    for (int i = 0; i < 8; i++) {
        int t = t0 + ty * 8 + i;
        *(ulonglong2*)&pp[t * IN_CH + tx * 8] =
            make_ulonglong2(acc2[i][0], acc2[i][1]);
        *(ulonglong2*)&pp[t * IN_CH + tx * 8 + 4] =
            make_ulonglong2(acc2[i][2], acc2[i][3]);
    }
}

// K1b: ve = sum over 37 chunk partials (deterministic reduce)
__global__ void __launch_bounds__(256) k1_reduce_kernel() {
    int idx = blockIdx.x * blockDim.x + threadIdx.x;   // 0..131071
    float s = 0.f;
#pragma unroll
    for (int c = 0; c < K1_NCHUNK; c++) s += g_part[c * (T_SEQ * IN_CH) + idx];
    g_ve[idx] = s;
}

// ============================================================================
// K2: gx[t][r] = b_ih[r] + sum_k ve[t][k]*w_ih[r][k]
// ============================================================================
__global__ void __launch_bounds__(256) gx_kernel(const float* __restrict__ w_ih,
                                                 const float* __restrict__ b_ih) {
    const int t = blockIdx.x;
    const int w = threadIdx.x >> 5, l = threadIdx.x & 31;
    float4 vv = *(const float4*)(g_ve + t * IN_CH + l * 4);
    for (int rr = 0; rr < 96; rr++) {
        int r = w * 96 + rr;
        float4 wv = *(const float4*)(w_ih + (size_t)r * IN_CH + l * 4);
        float p = vv.x * wv.x + vv.y * wv.y + vv.z * wv.z + vv.w * wv.w;
#pragma unroll
        for (int o = 16; o; o >>= 1) p += __shfl_xor_sync(0xffffffffu, p, o);
        if (l == 0) g_gx[t * G3 + r] = p + b_ih[r];
    }
}

// ============================================================================
// K3: sequential GRU, cluster of 8 CTAs x 256 threads.
// Thread (slot j, octant o): all 3 gate rows of slot, k in its octant
// (48 f32x2 weight regs). Reduce via shfl.xor in the 8-lane group (no
// __syncthreads). Activations via tanh.approx (no divisions). Lane o
// broadcasts hnew to peer o. One cluster.sync per step.
// ============================================================================
__device__ __forceinline__ void cluster_sync_() {
    asm volatile("barrier.cluster.arrive.aligned;" ::: "memory");
    asm volatile("barrier.cluster.wait.aligned;" ::: "memory");
}
__device__ __forceinline__ void st_remote_f32(uint32_t laddr, uint32_t peer, float v) {
    uint32_t raddr;
    asm volatile("mapa.shared::cluster.u32 %0, %1, %2;"
                 : "=r"(raddr) : "r"(laddr), "r"(peer));
    asm volatile("st.shared::cluster.f32 [%0], %1;" :: "r"(raddr), "f"(v) : "memory");
}
__device__ __forceinline__ float tanh_ap(float x) {
    float y;
    asm("tanh.approx.f32 %0, %1;" : "=f"(y) : "f"(x));
    return y;
}
__device__ __forceinline__ float sigmoid_ap(float x) {
    return fmaf(0.5f, tanh_ap(0.5f * x), 0.5f);
}

__global__ __launch_bounds__(256, 1) __cluster_dims__(8, 1, 1)
void gru_kernel(const float* __restrict__ w_hh, const float* __restrict__ b_hh) {
    __shared__ __align__(16) float sh_h[2][256];   // double-buffered hidden state

    const int tid = threadIdx.x;
    const int rank = blockIdx.x;
    const int j = tid >> 3;            // slot 0..31
    const int o = tid & 7;             // k-octant 0..7
    const int slot = rank * 32 + j;    // global h index owned by this group

    // Register weights: 3 gate rows x 16 pairs, pair index rotated by octant
    // so the per-step LDS of h hits 8 distinct banks per wavefront.
    unsigned long long wr[16], wz[16], wn[16];
#pragma unroll
    for (int i = 0; i < 16; i++) {
        int k = o * 32 + ((i + 2 * o) & 15) * 2;
        wr[i] = *(const unsigned long long*)(w_hh + (size_t)(slot)*256 + k);
        wz[i] = *(const unsigned long long*)(w_hh + (size_t)(256 + slot) * 256 + k);
        wn[i] = *(const unsigned long long*)(w_hh + (size_t)(512 + slot) * 256 + k);
    }
    const float bhr = b_hh[slot];
    const float bhz = b_hh[256 + slot];
    const float bhn = b_hh[512 + slot];

    sh_h[0][tid] = 0.f;   // h0 = 0
    sh_h[1][tid] = 0.f;
    __syncthreads();
    cluster_sync_();

    for (int t = 0; t < T_SEQ; t++) {
        const int cur = t & 1, nxt = cur ^ 1;

        // input gates for this step (independent of h; overlaps the matvec)
        const float gxr = g_gx[t * G3 + slot];
        const float gxz = g_gx[t * G3 + 256 + slot];
        const float gxn = g_gx[t * G3 + 512 + slot];
        const float hprev = sh_h[cur][slot];

        // octant matvec for 3 gate rows, f32x2 packed
        unsigned long long ar = 0ull, az = 0ull, an = 0ull;
        {
            const float* hb = &sh_h[cur][0];
#pragma unroll
            for (int i = 0; i < 16; i++) {
                int k = o * 32 + ((i + 2 * o) & 15) * 2;
                unsigned long long hv = *(const unsigned long long*)(hb + k);
                asm("fma.rn.f32x2 %0, %1, %2, %0;" : "+l"(ar) : "l"(wr[i]), "l"(hv));
                asm("fma.rn.f32x2 %0, %1, %2, %0;" : "+l"(az) : "l"(wz[i]), "l"(hv));
                asm("fma.rn.f32x2 %0, %1, %2, %0;" : "+l"(an) : "l"(wn[i]), "l"(hv));
            }
        }
        float pr, pz, pn;
        {
            float lo, hi;
            asm("mov.b64 {%0, %1}, %2;" : "=f"(lo), "=f"(hi) : "l"(ar)); pr = lo + hi;
            asm("mov.b64 {%0, %1}, %2;" : "=f"(lo), "=f"(hi) : "l"(az)); pz = lo + hi;
            asm("mov.b64 {%0, %1}, %2;" : "=f"(lo), "=f"(hi) : "l"(an)); pn = lo + hi;
        }
        // 8-lane group reduce (stays inside the warp; deterministic order)
#pragma unroll
        for (int d = 1; d < 8; d <<= 1) {
            pr += __shfl_xor_sync(0xffffffffu, pr, d);
            pz += __shfl_xor_sync(0xffffffffu, pz, d);
            pn += __shfl_xor_sync(0xffffffffu, pn, d);
        }

        // redundant epilogue in all 8 lanes (identical inputs -> identical hnew)
        const float r = sigmoid_ap(gxr + pr + bhr);
        const float z = sigmoid_ap(gxz + pz + bhz);
        const float n = tanh_ap(gxn + fmaf(r, pn + bhn, 0.f));
        const float hnew = n + z * (hprev - n);

        if (o == 0) g_hs[t * HID + slot] = hnew;
        // lane o delivers this slot's hnew to peer CTA o (1 store/thread)
        uint32_t laddr = (uint32_t)__cvta_generic_to_shared(&sh_h[nxt][slot]);
        st_remote_f32(laddr, (uint32_t)o, hnew);

        cluster_sync_();  // orders DSMEM stores before next step's reads
    }
}

// ============================================================================
// K4: logits = hs @ w_attn; alpha = softmax(logits); out = alpha @ hs
// ============================================================================
__global__ void __launch_bounds__(1024) attn_kernel(const float* __restrict__ w_attn,
                                                    float* __restrict__ out) {
    __shared__ float s_alpha[1024];
    __shared__ float s_red[1024];
    __shared__ float s_wa[256];
    const int tid = threadIdx.x;
    if (tid < 256) s_wa[tid] = w_attn[tid];
    __syncthreads();

    const int w = tid >> 5, l = tid & 31;
    for (int tt = 0; tt < 32; tt++) {
        int t = w * 32 + tt;
        const float* hr = g_hs + t * HID;
        float p = 0.f;
#pragma unroll
        for (int j = 0; j < 8; j++) p = fmaf(hr[l + 32 * j], s_wa[l + 32 * j], p);
#pragma unroll
        for (int o = 16; o; o >>= 1) p += __shfl_xor_sync(0xffffffffu, p, o);
        if (l == 0) s_alpha[t] = p;
    }
    __syncthreads();

    float v = s_alpha[tid];
    s_red[tid] = v;
    __syncthreads();
    for (int s = 512; s; s >>= 1) {
        if (tid < s) s_red[tid] = fmaxf(s_red[tid], s_red[tid + s]);
        __syncthreads();
    }
    float m = s_red[0];
    __syncthreads();
    float e = __expf(v - m);
    s_red[tid] = e;
    __syncthreads();
    for (int s = 512; s; s >>= 1) {
        if (tid < s) s_red[tid] = s_red[tid] + s_red[tid + s];
        __syncthreads();
    }
    float inv = 1.f / s_red[0];
    __syncthreads();
    s_alpha[tid] = e * inv;
    __syncthreads();

    const int j = tid & 255, seg = tid >> 8;
    float p = 0.f;
    const float* hp = g_hs + (size_t)seg * 256 * HID + j;
    const float* ap = s_alpha + seg * 256;
    for (int t = 0; t < 256; t++) p = fmaf(ap[t], hp[t * HID], p);
    s_red[tid] = p;
    __syncthreads();
    if (tid < 256)
        out[j] = (s_red[j] + s_red[256 + j]) + (s_red[512 + j] + s_red[768 + j]);
}

// ============================================================================
extern "C" void kernel_launch(void* const* d_in, const int* in_sizes, int n_in,
                              void* d_out, int out_size) {
    const float* X = nullptr;
    const float* H = nullptr;
    const float* w_ih = nullptr;
    const float* w_hh = nullptr;
    const float* b_ih = nullptr;
    const float* b_hh = nullptr;
    const float* w_attn = nullptr;
    for (int i = 0; i < n_in; i++) {
        int s = in_sizes[i];
        const float* p = (const float*)d_in[i];
        if (s == N_NODES * IN_CH)      X = p;
        else if (s == N_NODES * T_SEQ) H = p;
        else if (s == G3 * IN_CH)      w_ih = p;
        else if (s == G3 * HID)        w_hh = p;
        else if (s == G3) { if (!b_ih) b_ih = p; else b_hh = p; }
        else if (s == HID)             w_attn = p;
    }
    float* out = (float*)d_out;

    k1_kernel<<<dim3(8, K1_NCHUNK), 256>>>(H, X);
    k1_reduce_kernel<<<(T_SEQ * IN_CH) / 256, 256>>>();
    gx_kernel<<<T_SEQ, 256>>>(w_ih, b_ih);
    gru_kernel<<<8, 256>>>(w_hh, b_hh);
    attn_kernel<<<1, 1024>>>(w_attn, out);
}

// round 6
// speedup vs baseline: 3.1353x; 1.1119x over previous
#include <cuda_runtime.h>
#include <cstdint>
#include <cstddef>

#define N_NODES 100000
#define T_SEQ   1024
#define IN_CH   128
#define HID     256
#define G3      768     // 3*HID gate rows

// ---------------- scratch (device globals; no allocations allowed) ----------
#define K1_NCHUNK 37
#define K1_CHUNK  2720  // 85*32, 37*2720 = 100640 >= 100000 (guarded)

__device__ float g_part[K1_NCHUNK * T_SEQ * IN_CH];  // ~19.4 MB partials
__device__ float g_ve[T_SEQ * IN_CH];                // visit_emb [1024,128]
__device__ float g_gx[T_SEQ * G3];                   // input gates [1024,768]
__device__ float g_hs[T_SEQ * HID];                  // hidden states [1024,256]

// ============================================================================
// K1: part[c][t][i] = sum_{n in chunk c} H[n][t] * X[n][i]
// fp32 math via packed fma.rn.f32x2 (FFMA2): 2 FMAs per fma-pipe issue slot.
// ============================================================================
__global__ void __launch_bounds__(256, 2) k1_kernel(const float* __restrict__ H,
                                                    const float* __restrict__ X) {
    __shared__ __align__(16) float Hs[32][128];
    __shared__ __align__(16) float Xs[32][128];
    const int tid = threadIdx.x;
    const int tx = tid & 15, ty = tid >> 4;
    const int t0 = blockIdx.x * 128;
    const int n0 = blockIdx.y * K1_CHUNK;

    unsigned long long acc2[8][4];   // acc2[i][j] = (acc[i][2j], acc[i][2j+1])
#pragma unroll
    for (int i = 0; i < 8; i++)
#pragma unroll
        for (int j = 0; j < 4; j++) acc2[i][j] = 0ull;

    for (int nb = 0; nb < K1_CHUNK; nb += 32) {
#pragma unroll
        for (int v = 0; v < 4; v++) {
            int e = tid + v * 256;        // 0..1023 float4 slots
            int row = e >> 5;             // 0..31
            int c = (e & 31) << 2;        // 0..124 step 4
            int n = n0 + nb + row;
            float4 hv = make_float4(0.f, 0.f, 0.f, 0.f);
            float4 xv = make_float4(0.f, 0.f, 0.f, 0.f);
            if (n < N_NODES) {
                hv = *(const float4*)(H + (size_t)n * T_SEQ + t0 + c);
                xv = *(const float4*)(X + (size_t)n * IN_CH + c);
            }
            *(float4*)&Hs[row][c] = hv;
            *(float4*)&Xs[row][c] = xv;
        }
        __syncthreads();
#pragma unroll
        for (int kk = 0; kk < 32; kk++) {
            float a[8];
            *(float4*)&a[0] = *(const float4*)&Hs[kk][ty * 8];
            *(float4*)&a[4] = *(const float4*)&Hs[kk][ty * 8 + 4];
            unsigned long long bb[4];    // pair-packed B operands, free from SMEM
            *(ulonglong2*)&bb[0] = *(const ulonglong2*)&Xs[kk][tx * 8];
            *(ulonglong2*)&bb[2] = *(const ulonglong2*)&Xs[kk][tx * 8 + 4];
#pragma unroll
            for (int i = 0; i < 8; i++) {
                unsigned long long aa;
                unsigned int ai = __float_as_uint(a[i]);
                asm("mov.b64 %0, {%1, %1};" : "=l"(aa) : "r"(ai));
#pragma unroll
                for (int j = 0; j < 4; j++)
                    asm("fma.rn.f32x2 %0, %1, %2, %0;"
                        : "+l"(acc2[i][j]) : "l"(aa), "l"(bb[j]));
            }
        }
        __syncthreads();
    }

    float* pp = g_part + (size_t)blockIdx.y * (T_SEQ * IN_CH);
#pragma unroll
    for (int i = 0; i < 8; i++) {
        int t = t0 + ty * 8 + i;
        *(ulonglong2*)&pp[t * IN_CH + tx * 8] =
            make_ulonglong2(acc2[i][0], acc2[i][1]);
        *(ulonglong2*)&pp[t * IN_CH + tx * 8 + 4] =
            make_ulonglong2(acc2[i][2], acc2[i][3]);
    }
}

// K1b: ve = sum over 37 chunk partials (deterministic reduce)
__global__ void __launch_bounds__(256) k1_reduce_kernel() {
    int idx = blockIdx.x * blockDim.x + threadIdx.x;   // 0..131071
    float s = 0.f;
#pragma unroll
    for (int c = 0; c < K1_NCHUNK; c++) s += g_part[c * (T_SEQ * IN_CH) + idx];
    g_ve[idx] = s;
}

// ============================================================================
// K2: gx[t][r] = b_ih[r] + sum_k ve[t][k]*w_ih[r][k]
// ============================================================================
__global__ void __launch_bounds__(256) gx_kernel(const float* __restrict__ w_ih,
                                                 const float* __restrict__ b_ih) {
    const int t = blockIdx.x;
    const int w = threadIdx.x >> 5, l = threadIdx.x & 31;
    float4 vv = *(const float4*)(g_ve + t * IN_CH + l * 4);
    for (int rr = 0; rr < 96; rr++) {
        int r = w * 96 + rr;
        float4 wv = *(const float4*)(w_ih + (size_t)r * IN_CH + l * 4);
        float p = vv.x * wv.x + vv.y * wv.y + vv.z * wv.z + vv.w * wv.w;
#pragma unroll
        for (int o = 16; o; o >>= 1) p += __shfl_xor_sync(0xffffffffu, p, o);
        if (l == 0) g_gx[t * G3 + r] = p + b_ih[r];
    }
}

// ============================================================================
// K3: sequential GRU, cluster of 8 CTAs x 256 threads.
// Thread (slot j, octant o): all 3 gate rows of slot, k in its octant
// (48 f32x2 weight regs). Reduce via shfl.xor in 8-lane group.
// Handshake: 256 DSMEM stores -> __syncthreads -> 8 remote release-arrives
// on the peers' full barrier (double-buffered) -> try_wait.acquire.
// No cluster.sync in the loop (no 490cy barrier, no CCTL.IVALL L1 flush).
// Write-after-read safety: a producer's write to peer B's buffer b at step t
// is gated by the full-wait whose arrivals (release, after B's __syncthreads)
// happen-after B's reads of buffer b at step t-1.
// ============================================================================
__device__ __forceinline__ void cluster_sync_() {
    asm volatile("barrier.cluster.arrive.aligned;" ::: "memory");
    asm volatile("barrier.cluster.wait.aligned;" ::: "memory");
}
__device__ __forceinline__ void st_remote_f32(uint32_t laddr, uint32_t peer, float v) {
    uint32_t raddr;
    asm volatile("mapa.shared::cluster.u32 %0, %1, %2;"
                 : "=r"(raddr) : "r"(laddr), "r"(peer));
    asm volatile("st.shared::cluster.f32 [%0], %1;" :: "r"(raddr), "f"(v) : "memory");
}
__device__ __forceinline__ void arrive_remote(uint32_t lbar, uint32_t peer) {
    uint32_t raddr;
    asm volatile("mapa.shared::cluster.u32 %0, %1, %2;"
                 : "=r"(raddr) : "r"(lbar), "r"(peer));
    asm volatile("mbarrier.arrive.release.cluster.shared::cluster.b64 _, [%0];"
                 :: "r"(raddr) : "memory");
}
__device__ __forceinline__ void wait_parity_cl(uint32_t bar, uint32_t par) {
    uint32_t done;
    asm volatile(
        "{\n\t.reg .pred p;\n\t"
        "mbarrier.try_wait.parity.acquire.cluster.shared::cta.b64 p, [%1], %2, 0x989680;\n\t"
        "selp.b32 %0, 1, 0, p;\n\t}"
        : "=r"(done) : "r"(bar), "r"(par) : "memory");
    while (!done) {
        asm volatile(
            "{\n\t.reg .pred p;\n\t"
            "mbarrier.try_wait.parity.acquire.cluster.shared::cta.b64 p, [%1], %2, 0x989680;\n\t"
            "selp.b32 %0, 1, 0, p;\n\t}"
            : "=r"(done) : "r"(bar), "r"(par) : "memory");
    }
}
__device__ __forceinline__ float tanh_ap(float x) {
    float y;
    asm("tanh.approx.f32 %0, %1;" : "=f"(y) : "f"(x));
    return y;
}
__device__ __forceinline__ float sigmoid_ap(float x) {
    return fmaf(0.5f, tanh_ap(0.5f * x), 0.5f);
}

__global__ __launch_bounds__(256, 1) __cluster_dims__(8, 1, 1)
void gru_kernel(const float* __restrict__ w_hh, const float* __restrict__ b_hh) {
    __shared__ __align__(16) float sh_h[2][256];            // double-buffered h
    __shared__ __align__(8) unsigned long long sh_bar[2];   // full barrier per buf

    const int tid = threadIdx.x;
    const int rank = blockIdx.x;
    const int j = tid >> 3;            // slot 0..31
    const int o = tid & 7;             // k-octant 0..7
    const int slot = rank * 32 + j;    // global h index owned by this group

    // Register weights: 3 gate rows x 16 pairs, pair index rotated by octant
    // so the per-step LDS of h hits 8 distinct banks per wavefront.
    unsigned long long wr[16], wz[16], wn[16];
#pragma unroll
    for (int i = 0; i < 16; i++) {
        int k = o * 32 + ((i + 2 * o) & 15) * 2;
        wr[i] = *(const unsigned long long*)(w_hh + (size_t)(slot)*256 + k);
        wz[i] = *(const unsigned long long*)(w_hh + (size_t)(256 + slot) * 256 + k);
        wn[i] = *(const unsigned long long*)(w_hh + (size_t)(512 + slot) * 256 + k);
    }
    const float bhr = b_hh[slot];
    const float bhz = b_hh[256 + slot];
    const float bhn = b_hh[512 + slot];

    sh_h[0][tid] = 0.f;   // h0 = 0
    sh_h[1][tid] = 0.f;
    uint32_t bbase = (uint32_t)__cvta_generic_to_shared(&sh_bar[0]);
    if (tid == 0) {
        asm volatile("mbarrier.init.shared.b64 [%0], %1;" :: "r"(bbase),     "r"(8) : "memory");
        asm volatile("mbarrier.init.shared.b64 [%0], %1;" :: "r"(bbase + 8), "r"(8) : "memory");
    }
    __syncthreads();
    cluster_sync_();   // barriers + h0 visible cluster-wide

    for (int t = 0; t < T_SEQ; t++) {
        const int cur = t & 1, nxt = cur ^ 1;

        // issue gx loads (h-independent) before the wait to hide L1 latency
        const float gxr = g_gx[t * G3 + slot];
        const float gxz = g_gx[t * G3 + 256 + slot];
        const float gxn = g_gx[t * G3 + 512 + slot];

        if (t > 0) wait_parity_cl(bbase + 8u * (uint32_t)cur, ((t - 1) >> 1) & 1);

        const float hprev = sh_h[cur][slot];

        // octant matvec for 3 gate rows, f32x2 packed
        unsigned long long ar = 0ull, az = 0ull, an = 0ull;
        {
            const float* hb = &sh_h[cur][0];
#pragma unroll
            for (int i = 0; i < 16; i++) {
                int k = o * 32 + ((i + 2 * o) & 15) * 2;
                unsigned long long hv = *(const unsigned long long*)(hb + k);
                asm("fma.rn.f32x2 %0, %1, %2, %0;" : "+l"(ar) : "l"(wr[i]), "l"(hv));
                asm("fma.rn.f32x2 %0, %1, %2, %0;" : "+l"(az) : "l"(wz[i]), "l"(hv));
                asm("fma.rn.f32x2 %0, %1, %2, %0;" : "+l"(an) : "l"(wn[i]), "l"(hv));
            }
        }
        float pr, pz, pn;
        {
            float lo, hi;
            asm("mov.b64 {%0, %1}, %2;" : "=f"(lo), "=f"(hi) : "l"(ar)); pr = lo + hi;
            asm("mov.b64 {%0, %1}, %2;" : "=f"(lo), "=f"(hi) : "l"(az)); pz = lo + hi;
            asm("mov.b64 {%0, %1}, %2;" : "=f"(lo), "=f"(hi) : "l"(an)); pn = lo + hi;
        }
#pragma unroll
        for (int d = 1; d < 8; d <<= 1) {
            pr += __shfl_xor_sync(0xffffffffu, pr, d);
            pz += __shfl_xor_sync(0xffffffffu, pz, d);
            pn += __shfl_xor_sync(0xffffffffu, pn, d);
        }

        // redundant epilogue in all 8 lanes (identical inputs -> identical hnew)
        const float r = sigmoid_ap(gxr + pr + bhr);
        const float z = sigmoid_ap(gxz + pz + bhz);
        const float n = tanh_ap(gxn + r * (pn + bhn));
        const float hnew = n + z * (hprev - n);

        if (o == 0) g_hs[t * HID + slot] = hnew;

        if (t < T_SEQ - 1) {
            // deliver this slot's hnew to peer CTA o (1 DSMEM store/thread)
            uint32_t laddr = (uint32_t)__cvta_generic_to_shared(&sh_h[nxt][slot]);
            st_remote_f32(laddr, (uint32_t)o, hnew);
            __syncthreads();                  // all stores + all reads of cur done
            if (tid < 8) arrive_remote(bbase + 8u * (uint32_t)nxt, (uint32_t)tid);
        }
    }
    cluster_sync_();   // drain in-flight DSMEM traffic before exit
}

// ============================================================================
// K4: logits = hs @ w_attn; alpha = softmax(logits); out = alpha @ hs
// ============================================================================
__global__ void __launch_bounds__(1024) attn_kernel(const float* __restrict__ w_attn,
                                                    float* __restrict__ out) {
    __shared__ float s_alpha[1024];
    __shared__ float s_red[1024];
    __shared__ float s_wa[256];
    const int tid = threadIdx.x;
    if (tid < 256) s_wa[tid] = w_attn[tid];
    __syncthreads();

    const int w = tid >> 5, l = tid & 31;
    for (int tt = 0; tt < 32; tt++) {
        int t = w * 32 + tt;
        const float* hr = g_hs + t * HID;
        float p = 0.f;
#pragma unroll
        for (int j = 0; j < 8; j++) p = fmaf(hr[l + 32 * j], s_wa[l + 32 * j], p);
#pragma unroll
        for (int o = 16; o; o >>= 1) p += __shfl_xor_sync(0xffffffffu, p, o);
        if (l == 0) s_alpha[t] = p;
    }
    __syncthreads();

    float v = s_alpha[tid];
    s_red[tid] = v;
    __syncthreads();
    for (int s = 512; s; s >>= 1) {
        if (tid < s) s_red[tid] = fmaxf(s_red[tid], s_red[tid + s]);
        __syncthreads();
    }
    float m = s_red[0];
    __syncthreads();
    float e = __expf(v - m);
    s_red[tid] = e;
    __syncthreads();
    for (int s = 512; s; s >>= 1) {
        if (tid < s) s_red[tid] = s_red[tid] + s_red[tid + s];
        __syncthreads();
    }
    float inv = 1.f / s_red[0];
    __syncthreads();
    s_alpha[tid] = e * inv;
    __syncthreads();

    const int j = tid & 255, seg = tid >> 8;
    float p = 0.f;
    const float* hp = g_hs + (size_t)seg * 256 * HID + j;
    const float* ap = s_alpha + seg * 256;
    for (int t = 0; t < 256; t++) p = fmaf(ap[t], hp[t * HID], p);
    s_red[tid] = p;
    __syncthreads();
    if (tid < 256)
        out[j] = (s_red[j] + s_red[256 + j]) + (s_red[512 + j] + s_red[768 + j]);
}

// ============================================================================
extern "C" void kernel_launch(void* const* d_in, const int* in_sizes, int n_in,
                              void* d_out, int out_size) {
    const float* X = nullptr;
    const float* H = nullptr;
    const float* w_ih = nullptr;
    const float* w_hh = nullptr;
    const float* b_ih = nullptr;
    const float* b_hh = nullptr;
    const float* w_attn = nullptr;
    for (int i = 0; i < n_in; i++) {
        int s = in_sizes[i];
        const float* p = (const float*)d_in[i];
        if (s == N_NODES * IN_CH)      X = p;
        else if (s == N_NODES * T_SEQ) H = p;
        else if (s == G3 * IN_CH)      w_ih = p;
        else if (s == G3 * HID)        w_hh = p;
        else if (s == G3) { if (!b_ih) b_ih = p; else b_hh = p; }
        else if (s == HID)             w_attn = p;
    }
    float* out = (float*)d_out;

    k1_kernel<<<dim3(8, K1_NCHUNK), 256>>>(H, X);
    k1_reduce_kernel<<<(T_SEQ * IN_CH) / 256, 256>>>();
    gx_kernel<<<T_SEQ, 256>>>(w_ih, b_ih);
    gru_kernel<<<8, 256>>>(w_hh, b_hh);
    attn_kernel<<<1, 1024>>>(w_attn, out);
}

// round 8
// speedup vs baseline: 3.4311x; 1.0943x over previous
#include <cuda_runtime.h>
#include <cuda_bf16.h>
#include <cstdint>
#include <cstddef>

#define N_NODES 100000
#define T_SEQ   1024
#define IN_CH   128
#define HID     256
#define G3      768     // 3*HID gate rows

// ---------------- scratch (device globals; no allocations allowed) ----------
#define K1_NCHUNK 37
#define K1_CHUNK  2752  // 43*64; 37*2752 = 101824 >= 100000 (guarded)
#define NSLICES   43    // K-slices of 64 per chunk

__device__ float g_part[K1_NCHUNK * T_SEQ * IN_CH];  // ~19.4 MB partials
__device__ float g_ve[T_SEQ * IN_CH];                // visit_emb [1024,128]
__device__ float g_gx[T_SEQ * G3];                   // input gates [1024,768]
__device__ float g_hs[T_SEQ * HID];                  // hidden states [1024,256]

// ============================================================================
// K1 (tensor, legacy mma.sync — no sm_103a-only instructions):
// part[c][t][i] = sum_{n in chunk c} H[n][t] * X[n][i]
// bf16 hi/lo split, 3 products (hi*hi + hi*lo + lo*hi), fp32 accumulate.
// A[m=t][k=n] (transposed from H on store), B[n=i][k=n] from X.
// SMEM word layout: tile[row][kpair] with row stride 36 words (4 mod 32
// => conflict-free for both the STS pattern and the fragment LDS pattern).
// ============================================================================
#define WSTR 36                       // words per tile row
#define OFF_AH 0
#define OFF_AL (128 * WSTR)
#define OFF_BH (256 * WSTR)
#define OFF_BL (384 * WSTR)
#define K1_SMEM_BYTES (512 * WSTR * 4)

__device__ __forceinline__ void mma_bf16(float& c0, float& c1, float& c2, float& c3,
                                         uint32_t a0, uint32_t a1, uint32_t a2,
                                         uint32_t a3, uint32_t b0, uint32_t b1) {
    asm volatile(
        "mma.sync.aligned.m16n8k16.row.col.f32.bf16.bf16.f32 "
        "{%0,%1,%2,%3}, {%4,%5,%6,%7}, {%8,%9}, {%0,%1,%2,%3};"
        : "+f"(c0), "+f"(c1), "+f"(c2), "+f"(c3)
        : "r"(a0), "r"(a1), "r"(a2), "r"(a3), "r"(b0), "r"(b1));
}

__global__ void __launch_bounds__(512, 1) k1h_kernel(const float* __restrict__ H,
                                                     const float* __restrict__ X) {
    extern __shared__ uint32_t smw[];   // 512*36 words

    const int tid = threadIdx.x;
    const int t0 = blockIdx.x * 128;
    const int n0 = blockIdx.y * K1_CHUNK;

    // loader mapping: kp = k-pair 0..31 (k = 2kp, 2kp+1), mg = row-octet 0..15
    const int kp = tid & 31;
    const int mg = tid >> 5;            // rows mg*8 .. mg*8+7
    const float4 z4 = make_float4(0.f, 0.f, 0.f, 0.f);

    // warp mapping for MMA: 4x4 warp grid, each warp 32(M) x 32(N)
    const int wid = tid >> 5, lane = tid & 31;
    const int wm = wid >> 2, wn = wid & 3;
    const int lr = lane >> 2, lc = lane & 3;

    float c[2][4][4];
#pragma unroll
    for (int mt = 0; mt < 2; mt++)
#pragma unroll
        for (int nt = 0; nt < 4; nt++)
#pragma unroll
            for (int r = 0; r < 4; r++) c[mt][nt][r] = 0.f;

    // prefetch registers: H rows (na, na+1) x 8 m-cols; X rows x 8 i-cols
    float4 h0a, h0b, h1a, h1b, x0a, x0b, x1a, x1b;
    {
        int na = n0 + 2 * kp;
        int m0 = mg * 8;
        bool v0 = na < N_NODES, v1 = na + 1 < N_NODES;
        h0a = v0 ? *(const float4*)(H + (size_t)na * T_SEQ + t0 + m0) : z4;
        h0b = v0 ? *(const float4*)(H + (size_t)na * T_SEQ + t0 + m0 + 4) : z4;
        h1a = v1 ? *(const float4*)(H + (size_t)(na + 1) * T_SEQ + t0 + m0) : z4;
        h1b = v1 ? *(const float4*)(H + (size_t)(na + 1) * T_SEQ + t0 + m0 + 4) : z4;
        x0a = v0 ? *(const float4*)(X + (size_t)na * IN_CH + m0) : z4;
        x0b = v0 ? *(const float4*)(X + (size_t)na * IN_CH + m0 + 4) : z4;
        x1a = v1 ? *(const float4*)(X + (size_t)(na + 1) * IN_CH + m0) : z4;
        x1b = v1 ? *(const float4*)(X + (size_t)(na + 1) * IN_CH + m0 + 4) : z4;
    }

    for (int s = 0; s < NSLICES; s++) {
        // ---- convert + transposed packed stores (prefetched slice s) ----
        {
            const float* e0[2] = {&h0a.x, &x0a.x};
            const float* f0[2] = {&h0b.x, &x0b.x};
            const float* e1[2] = {&h1a.x, &x1a.x};
            const float* f1[2] = {&h1b.x, &x1b.x};
            const int offh[2] = {OFF_AH, OFF_BH};
            const int offl[2] = {OFF_AL, OFF_BL};
#pragma unroll
            for (int tsel = 0; tsel < 2; tsel++) {
#pragma unroll
                for (int j = 0; j < 8; j++) {
                    float v0 = (j < 4) ? e0[tsel][j] : f0[tsel][j - 4];
                    float v1 = (j < 4) ? e1[tsel][j] : f1[tsel][j - 4];
                    __nv_bfloat162 hi2 = __floats2bfloat162_rn(v0, v1);
                    float l0 = v0 - __bfloat162float(hi2.x);
                    float l1 = v1 - __bfloat162float(hi2.y);
                    __nv_bfloat162 lo2 = __floats2bfloat162_rn(l0, l1);
                    int m = mg * 8 + j;
                    smw[offh[tsel] + m * WSTR + kp] = *(uint32_t*)&hi2;
                    smw[offl[tsel] + m * WSTR + kp] = *(uint32_t*)&lo2;
                }
            }
        }

        // ---- prefetch slice s+1 (in flight during MMA phase) ----
        if (s + 1 < NSLICES) {
            int na = n0 + (s + 1) * 64 + 2 * kp;
            int m0 = mg * 8;
            bool v0 = na < N_NODES, v1 = na + 1 < N_NODES;
            h0a = v0 ? *(const float4*)(H + (size_t)na * T_SEQ + t0 + m0) : z4;
            h0b = v0 ? *(const float4*)(H + (size_t)na * T_SEQ + t0 + m0 + 4) : z4;
            h1a = v1 ? *(const float4*)(H + (size_t)(na + 1) * T_SEQ + t0 + m0) : z4;
            h1b = v1 ? *(const float4*)(H + (size_t)(na + 1) * T_SEQ + t0 + m0 + 4) : z4;
            x0a = v0 ? *(const float4*)(X + (size_t)na * IN_CH + m0) : z4;
            x0b = v0 ? *(const float4*)(X + (size_t)na * IN_CH + m0 + 4) : z4;
            x1a = v1 ? *(const float4*)(X + (size_t)(na + 1) * IN_CH + m0) : z4;
            x1b = v1 ? *(const float4*)(X + (size_t)(na + 1) * IN_CH + m0 + 4) : z4;
        }

        __syncthreads();   // tiles visible

        // ---- MMA phase: 4 k-steps of 16 ----
#pragma unroll
        for (int ks = 0; ks < 4; ks++) {
            const int ksw = ks * 8;
            uint32_t ah[2][4], al[2][4], bh[4][2], bl[4][2];
#pragma unroll
            for (int mt = 0; mt < 2; mt++) {
                int row = wm * 32 + mt * 16 + lr;
                const uint32_t* pa = smw + row * WSTR + ksw + lc;
                ah[mt][0] = pa[OFF_AH];
                ah[mt][1] = pa[OFF_AH + 8 * WSTR];
                ah[mt][2] = pa[OFF_AH + 4];
                ah[mt][3] = pa[OFF_AH + 8 * WSTR + 4];
                al[mt][0] = pa[OFF_AL];
                al[mt][1] = pa[OFF_AL + 8 * WSTR];
                al[mt][2] = pa[OFF_AL + 4];
                al[mt][3] = pa[OFF_AL + 8 * WSTR + 4];
            }
#pragma unroll
            for (int nt = 0; nt < 4; nt++) {
                int nrow = wn * 32 + nt * 8 + lr;
                const uint32_t* pb = smw + nrow * WSTR + ksw + lc;
                bh[nt][0] = pb[OFF_BH];
                bh[nt][1] = pb[OFF_BH + 4];
                bl[nt][0] = pb[OFF_BL];
                bl[nt][1] = pb[OFF_BL + 4];
            }
#pragma unroll
            for (int mt = 0; mt < 2; mt++)
#pragma unroll
                for (int nt = 0; nt < 4; nt++) {
                    float* cc = c[mt][nt];
                    mma_bf16(cc[0], cc[1], cc[2], cc[3],
                             ah[mt][0], ah[mt][1], ah[mt][2], ah[mt][3],
                             bh[nt][0], bh[nt][1]);
                    mma_bf16(cc[0], cc[1], cc[2], cc[3],
                             ah[mt][0], ah[mt][1], ah[mt][2], ah[mt][3],
                             bl[nt][0], bl[nt][1]);
                    mma_bf16(cc[0], cc[1], cc[2], cc[3],
                             al[mt][0], al[mt][1], al[mt][2], al[mt][3],
                             bh[nt][0], bh[nt][1]);
                }
        }

        __syncthreads();   // MMA reads done before next slice's stores
    }

    // ---- epilogue: write C fragments to partial buffer ----
    float* pp = g_part + (size_t)blockIdx.y * (T_SEQ * IN_CH);
#pragma unroll
    for (int mt = 0; mt < 2; mt++) {
#pragma unroll
        for (int nt = 0; nt < 4; nt++) {
            int row0 = wm * 32 + mt * 16 + lr;
            int col = wn * 32 + nt * 8 + lc * 2;
            *(float2*)(pp + (size_t)(t0 + row0) * IN_CH + col) =
                make_float2(c[mt][nt][0], c[mt][nt][1]);
            *(float2*)(pp + (size_t)(t0 + row0 + 8) * IN_CH + col) =
                make_float2(c[mt][nt][2], c[mt][nt][3]);
        }
    }
}

// K1b: ve = sum over 37 chunk partials (deterministic reduce)
__global__ void __launch_bounds__(256) k1_reduce_kernel() {
    int idx = blockIdx.x * blockDim.x + threadIdx.x;   // 0..131071
    float s = 0.f;
#pragma unroll
    for (int c = 0; c < K1_NCHUNK; c++) s += g_part[c * (T_SEQ * IN_CH) + idx];
    g_ve[idx] = s;
}

// ============================================================================
// K2: gx[t][r] = b_ih[r] + sum_k ve[t][k]*w_ih[r][k]
// ============================================================================
__global__ void __launch_bounds__(256) gx_kernel(const float* __restrict__ w_ih,
                                                 const float* __restrict__ b_ih) {
    const int t = blockIdx.x;
    const int w = threadIdx.x >> 5, l = threadIdx.x & 31;
    float4 vv = *(const float4*)(g_ve + t * IN_CH + l * 4);
    for (int rr = 0; rr < 96; rr++) {
        int r = w * 96 + rr;
        float4 wv = *(const float4*)(w_ih + (size_t)r * IN_CH + l * 4);
        float p = vv.x * wv.x + vv.y * wv.y + vv.z * wv.z + vv.w * wv.w;
#pragma unroll
        for (int o = 16; o; o >>= 1) p += __shfl_xor_sync(0xffffffffu, p, o);
        if (l == 0) g_gx[t * G3 + r] = p + b_ih[r];
    }
}

// ============================================================================
// K3: sequential GRU (unchanged from round 6 — proven 892us)
// ============================================================================
__device__ __forceinline__ void cluster_sync_() {
    asm volatile("barrier.cluster.arrive.aligned;" ::: "memory");
    asm volatile("barrier.cluster.wait.aligned;" ::: "memory");
}
__device__ __forceinline__ void st_remote_f32(uint32_t laddr, uint32_t peer, float v) {
    uint32_t raddr;
    asm volatile("mapa.shared::cluster.u32 %0, %1, %2;"
                 : "=r"(raddr) : "r"(laddr), "r"(peer));
    asm volatile("st.shared::cluster.f32 [%0], %1;" :: "r"(raddr), "f"(v) : "memory");
}
__device__ __forceinline__ void arrive_remote(uint32_t lbar, uint32_t peer) {
    uint32_t raddr;
    asm volatile("mapa.shared::cluster.u32 %0, %1, %2;"
                 : "=r"(raddr) : "r"(lbar), "r"(peer));
    asm volatile("mbarrier.arrive.release.cluster.shared::cluster.b64 _, [%0];"
                 :: "r"(raddr) : "memory");
}
__device__ __forceinline__ void wait_parity_cl(uint32_t bar, uint32_t par) {
    uint32_t done;
    do {
        asm volatile(
            "{\n\t.reg .pred p;\n\t"
            "mbarrier.try_wait.parity.acquire.cluster.shared::cta.b64 p, [%1], %2, 0x989680;\n\t"
            "selp.b32 %0, 1, 0, p;\n\t}"
            : "=r"(done) : "r"(bar), "r"(par) : "memory");
    } while (!done);
}
__device__ __forceinline__ float tanh_ap(float x) {
    float y;
    asm("tanh.approx.f32 %0, %1;" : "=f"(y) : "f"(x));
    return y;
}
__device__ __forceinline__ float sigmoid_ap(float x) {
    return fmaf(0.5f, tanh_ap(0.5f * x), 0.5f);
}

__global__ __launch_bounds__(256, 1) __cluster_dims__(8, 1, 1)
void gru_kernel(const float* __restrict__ w_hh, const float* __restrict__ b_hh) {
    __shared__ __align__(16) float sh_h[2][256];            // double-buffered h
    __shared__ __align__(8) unsigned long long sh_bar[2];   // full barrier per buf

    const int tid = threadIdx.x;
    const int rank = blockIdx.x;
    const int j = tid >> 3;            // slot 0..31
    const int o = tid & 7;             // k-octant 0..7
    const int slot = rank * 32 + j;    // global h index owned by this group

    unsigned long long wr[16], wz[16], wn[16];
#pragma unroll
    for (int i = 0; i < 16; i++) {
        int k = o * 32 + ((i + 2 * o) & 15) * 2;
        wr[i] = *(const unsigned long long*)(w_hh + (size_t)(slot)*256 + k);
        wz[i] = *(const unsigned long long*)(w_hh + (size_t)(256 + slot) * 256 + k);
        wn[i] = *(const unsigned long long*)(w_hh + (size_t)(512 + slot) * 256 + k);
    }
    const float bhr = b_hh[slot];
    const float bhz = b_hh[256 + slot];
    const float bhn = b_hh[512 + slot];

    sh_h[0][tid] = 0.f;
    sh_h[1][tid] = 0.f;
    uint32_t bbase = (uint32_t)__cvta_generic_to_shared(&sh_bar[0]);
    if (tid == 0) {
        asm volatile("mbarrier.init.shared.b64 [%0], %1;" :: "r"(bbase),     "r"(8) : "memory");
        asm volatile("mbarrier.init.shared.b64 [%0], %1;" :: "r"(bbase + 8), "r"(8) : "memory");
    }
    __syncthreads();
    cluster_sync_();

    for (int t = 0; t < T_SEQ; t++) {
        const int cur = t & 1, nxt = cur ^ 1;

        const float gxr = g_gx[t * G3 + slot];
        const float gxz = g_gx[t * G3 + 256 + slot];
        const float gxn = g_gx[t * G3 + 512 + slot];

        if (t > 0) wait_parity_cl(bbase + 8u * (uint32_t)cur, ((t - 1) >> 1) & 1);

        const float hprev = sh_h[cur][slot];

        unsigned long long ar = 0ull, az = 0ull, an = 0ull;
        {
            const float* hb = &sh_h[cur][0];
#pragma unroll
            for (int i = 0; i < 16; i++) {
                int k = o * 32 + ((i + 2 * o) & 15) * 2;
                unsigned long long hv = *(const unsigned long long*)(hb + k);
                asm("fma.rn.f32x2 %0, %1, %2, %0;" : "+l"(ar) : "l"(wr[i]), "l"(hv));
                asm("fma.rn.f32x2 %0, %1, %2, %0;" : "+l"(az) : "l"(wz[i]), "l"(hv));
                asm("fma.rn.f32x2 %0, %1, %2, %0;" : "+l"(an) : "l"(wn[i]), "l"(hv));
            }
        }
        float pr, pz, pn;
        {
            float lo, hi;
            asm("mov.b64 {%0, %1}, %2;" : "=f"(lo), "=f"(hi) : "l"(ar)); pr = lo + hi;
            asm("mov.b64 {%0, %1}, %2;" : "=f"(lo), "=f"(hi) : "l"(az)); pz = lo + hi;
            asm("mov.b64 {%0, %1}, %2;" : "=f"(lo), "=f"(hi) : "l"(an)); pn = lo + hi;
        }
#pragma unroll
        for (int d = 1; d < 8; d <<= 1) {
            pr += __shfl_xor_sync(0xffffffffu, pr, d);
            pz += __shfl_xor_sync(0xffffffffu, pz, d);
            pn += __shfl_xor_sync(0xffffffffu, pn, d);
        }

        const float r = sigmoid_ap(gxr + pr + bhr);
        const float z = sigmoid_ap(gxz + pz + bhz);
        const float n = tanh_ap(gxn + r * (pn + bhn));
        const float hnew = n + z * (hprev - n);

        if (o == 0) g_hs[t * HID + slot] = hnew;

        if (t < T_SEQ - 1) {
            uint32_t laddr = (uint32_t)__cvta_generic_to_shared(&sh_h[nxt][slot]);
            st_remote_f32(laddr, (uint32_t)o, hnew);
            __syncthreads();
            if (tid < 8) arrive_remote(bbase + 8u * (uint32_t)nxt, (uint32_t)tid);
        }
    }
    cluster_sync_();
}

// ============================================================================
// K4: logits = hs @ w_attn; alpha = softmax(logits); out = alpha @ hs
// ============================================================================
__global__ void __launch_bounds__(1024) attn_kernel(const float* __restrict__ w_attn,
                                                    float* __restrict__ out) {
    __shared__ float s_alpha[1024];
    __shared__ float s_red[1024];
    __shared__ float s_wa[256];
    const int tid = threadIdx.x;
    if (tid < 256) s_wa[tid] = w_attn[tid];
    __syncthreads();

    const int w = tid >> 5, l = tid & 31;
    for (int tt = 0; tt < 32; tt++) {
        int t = w * 32 + tt;
        const float* hr = g_hs + t * HID;
        float p = 0.f;
#pragma unroll
        for (int j = 0; j < 8; j++) p = fmaf(hr[l + 32 * j], s_wa[l + 32 * j], p);
#pragma unroll
        for (int o = 16; o; o >>= 1) p += __shfl_xor_sync(0xffffffffu, p, o);
        if (l == 0) s_alpha[t] = p;
    }
    __syncthreads();

    float v = s_alpha[tid];
    s_red[tid] = v;
    __syncthreads();
    for (int s = 512; s; s >>= 1) {
        if (tid < s) s_red[tid] = fmaxf(s_red[tid], s_red[tid + s]);
        __syncthreads();
    }
    float m = s_red[0];
    __syncthreads();
    float e = __expf(v - m);
    s_red[tid] = e;
    __syncthreads();
    for (int s = 512; s; s >>= 1) {
        if (tid < s) s_red[tid] = s_red[tid] + s_red[tid + s];
        __syncthreads();
    }
    float inv = 1.f / s_red[0];
    __syncthreads();
    s_alpha[tid] = e * inv;
    __syncthreads();

    const int j = tid & 255, seg = tid >> 8;
    float p = 0.f;
    const float* hp = g_hs + (size_t)seg * 256 * HID + j;
    const float* ap = s_alpha + seg * 256;
    for (int t = 0; t < 256; t++) p = fmaf(ap[t], hp[t * HID], p);
    s_red[tid] = p;
    __syncthreads();
    if (tid < 256)
        out[j] = (s_red[j] + s_red[256 + j]) + (s_red[512 + j] + s_red[768 + j]);
}

// ============================================================================
extern "C" void kernel_launch(void* const* d_in, const int* in_sizes, int n_in,
                              void* d_out, int out_size) {
    const float* X = nullptr;
    const float* H = nullptr;
    const float* w_ih = nullptr;
    const float* w_hh = nullptr;
    const float* b_ih = nullptr;
    const float* b_hh = nullptr;
    const float* w_attn = nullptr;
    for (int i = 0; i < n_in; i++) {
        int s = in_sizes[i];
        const float* p = (const float*)d_in[i];
        if (s == N_NODES * IN_CH)      X = p;
        else if (s == N_NODES * T_SEQ) H = p;
        else if (s == G3 * IN_CH)      w_ih = p;
        else if (s == G3 * HID)        w_hh = p;
        else if (s == G3) { if (!b_ih) b_ih = p; else b_hh = p; }
        else if (s == HID)             w_attn = p;
    }
    float* out = (float*)d_out;

    cudaFuncSetAttribute(k1h_kernel, cudaFuncAttributeMaxDynamicSharedMemorySize,
                         K1_SMEM_BYTES);

    k1h_kernel<<<dim3(8, K1_NCHUNK), 512, K1_SMEM_BYTES>>>(H, X);
    k1_reduce_kernel<<<(T_SEQ * IN_CH) / 256, 256>>>();
    gx_kernel<<<T_SEQ, 256>>>(w_ih, b_ih);
    gru_kernel<<<8, 256>>>(w_hh, b_hh);
    attn_kernel<<<1, 1024>>>(w_attn, out);
}

// round 9
// speedup vs baseline: 3.7212x; 1.0845x over previous
#include <cuda_runtime.h>
#include <cuda_bf16.h>
#include <cstdint>
#include <cstddef>

#define N_NODES 100000
#define T_SEQ   1024
#define IN_CH   128
#define HID     256
#define G3      768     // 3*HID gate rows

// ---------------- scratch (device globals; no allocations allowed) ----------
#define K1_NCHUNK 37
#define K1_CHUNK  2752  // 43*64; 37*2752 = 101824 >= 100000 (guarded)
#define NSLICES   43    // K-slices of 64 per chunk

__device__ float g_part[K1_NCHUNK * T_SEQ * IN_CH];  // ~19.4 MB partials
__device__ float g_ve[T_SEQ * IN_CH];                // visit_emb [1024,128]
__device__ float g_gx[T_SEQ * G3];                   // input gates [1024,768]
__device__ float g_hs[T_SEQ * HID];                  // hidden states [1024,256]

// ============================================================================
// K1 (tensor, legacy mma.sync; cp.async staged, swizzled SMEM transpose):
// part[c][t][i] = sum_{n in chunk c} H[n][t] * X[n][i]
// bf16 hi/lo split, 3 products, fp32 accumulate.
// Staging: f32 [64 rows x 128 cols], row stride 512B, 16B-chunk swizzle
//   j' = j ^ ((r>>1)&7)  (cp.async dst stays 16B aligned; the transposed
//   LDS.128 read puts 8 distinct chunks per 8-lane phase -> conflict-free).
// Tiles: bf16-pair words [row][kpair], row stride 36 words (as round 8).
// ============================================================================
#define WSTR 36                       // words per tile row
#define STG_ROW 128                   // words per staging row (512B)
#define STG_MAT (64 * STG_ROW)        // words per staging matrix (8192)
#define TILE_BASE (4 * STG_MAT)       // staging: [buf][H/X]
#define OFF_AH (TILE_BASE + 0)
#define OFF_AL (TILE_BASE + 128 * WSTR)
#define OFF_BH (TILE_BASE + 256 * WSTR)
#define OFF_BL (TILE_BASE + 384 * WSTR)
#define K1_SMEM_BYTES ((TILE_BASE + 512 * WSTR) * 4)   // 204800 B

__device__ __forceinline__ void mma_bf16(float& c0, float& c1, float& c2, float& c3,
                                         uint32_t a0, uint32_t a1, uint32_t a2,
                                         uint32_t a3, uint32_t b0, uint32_t b1) {
    asm volatile(
        "mma.sync.aligned.m16n8k16.row.col.f32.bf16.bf16.f32 "
        "{%0,%1,%2,%3}, {%4,%5,%6,%7}, {%8,%9}, {%0,%1,%2,%3};"
        : "+f"(c0), "+f"(c1), "+f"(c2), "+f"(c3)
        : "r"(a0), "r"(a1), "r"(a2), "r"(a3), "r"(b0), "r"(b1));
}

__device__ __forceinline__ void k1_issue_slice(const float* __restrict__ H,
                                               const float* __restrict__ X,
                                               int n0s, int t0, int buf,
                                               uint32_t smb, int tid) {
    const uint32_t stH = smb + (uint32_t)((buf * 2 + 0) * STG_MAT) * 4u;
    const uint32_t stX = smb + (uint32_t)((buf * 2 + 1) * STG_MAT) * 4u;
#pragma unroll
    for (int i = 0; i < 4; i++) {
        int ch = tid + i * 512;          // 0..2047
        int r = ch >> 5;                 // staging row 0..63
        int j = ch & 31;                 // 16B chunk within row
        int js = j ^ ((r >> 1) & 7);     // swizzle (low 3 bits)
        uint32_t doff = (uint32_t)(r * 512 + js * 16);
        int n = n0s + r;
        if (n < N_NODES) {
            const float* gH = H + (size_t)n * T_SEQ + t0 + j * 4;
            const float* gX = X + (size_t)n * IN_CH + j * 4;
            asm volatile("cp.async.ca.shared.global [%0], [%1], 16;"
                         :: "r"(stH + doff), "l"(gH));
            asm volatile("cp.async.ca.shared.global [%0], [%1], 16;"
                         :: "r"(stX + doff), "l"(gX));
        } else {
            asm volatile("st.shared.v4.u32 [%0], {%1,%1,%1,%1};"
                         :: "r"(stH + doff), "r"(0u) : "memory");
            asm volatile("st.shared.v4.u32 [%0], {%1,%1,%1,%1};"
                         :: "r"(stX + doff), "r"(0u) : "memory");
        }
    }
}

__global__ void __launch_bounds__(512, 1) k1h_kernel(const float* __restrict__ H,
                                                     const float* __restrict__ X) {
    extern __shared__ uint32_t smw[];
    float* stf = (float*)smw;
    uint32_t smb;
    asm("{ .reg .u64 t; cvta.to.shared.u64 t, %1; cvt.u32.u64 %0, t; }"
        : "=r"(smb) : "l"((const void*)smw));

    const int tid = threadIdx.x;
    const int t0 = blockIdx.x * 128;
    const int n0 = blockIdx.y * K1_CHUNK;

    // convert mapping: kp = k-pair 0..31 (k = 2kp,2kp+1), mg = row-octet 0..15
    const int kp = tid & 31;
    const int mg = tid >> 5;
    const int kx = kp & 7;

    // warp mapping for MMA: 4x4 warp grid, each warp 32(M) x 32(N)
    const int wid = tid >> 5, lane = tid & 31;
    const int wm = wid >> 2, wn = wid & 3;
    const int lr = lane >> 2, lc = lane & 3;

    float c[2][4][4];
#pragma unroll
    for (int mt = 0; mt < 2; mt++)
#pragma unroll
        for (int nt = 0; nt < 4; nt++)
#pragma unroll
            for (int r = 0; r < 4; r++) c[mt][nt][r] = 0.f;

    // prologue: slice 0 -> buf 0
    k1_issue_slice(H, X, n0, t0, 0, smb, tid);
    asm volatile("cp.async.commit_group;" ::: "memory");

    for (int s = 0; s < NSLICES; s++) {
        const int buf = s & 1;

        if (s + 1 < NSLICES) {
            k1_issue_slice(H, X, n0 + (s + 1) * 64, t0, buf ^ 1, smb, tid);
            asm volatile("cp.async.commit_group;" ::: "memory");
            asm volatile("cp.async.wait_group 1;" ::: "memory");
        } else {
            asm volatile("cp.async.wait_group 0;" ::: "memory");
        }
        __syncthreads();   // staging[buf] visible to all

        // ---- convert: transposed LDS from staging, bf16 hi/lo STS to tiles --
#pragma unroll
        for (int tsel = 0; tsel < 2; tsel++) {
            const int so = (buf * 2 + tsel) * STG_MAT;
            const int offh = tsel ? OFF_BH : OFF_AH;
            const int offl = tsel ? OFF_BL : OFF_AL;
            const float* r0p = stf + so + (2 * kp) * STG_ROW;
            const float* r1p = stf + so + (2 * kp + 1) * STG_ROW;
            float4 v00 = *(const float4*)(r0p + (((2 * mg)     ^ kx) << 2));
            float4 v01 = *(const float4*)(r0p + (((2 * mg + 1) ^ kx) << 2));
            float4 v10 = *(const float4*)(r1p + (((2 * mg)     ^ kx) << 2));
            float4 v11 = *(const float4*)(r1p + (((2 * mg + 1) ^ kx) << 2));
            const float* e0 = &v00.x;
            const float* f0 = &v01.x;
            const float* e1 = &v10.x;
            const float* f1 = &v11.x;
#pragma unroll
            for (int j = 0; j < 8; j++) {
                float v0 = (j < 4) ? e0[j] : f0[j - 4];
                float v1 = (j < 4) ? e1[j] : f1[j - 4];
                __nv_bfloat162 hi2 = __floats2bfloat162_rn(v0, v1);
                float l0 = v0 - __bfloat162float(hi2.x);
                float l1 = v1 - __bfloat162float(hi2.y);
                __nv_bfloat162 lo2 = __floats2bfloat162_rn(l0, l1);
                int m = mg * 8 + j;
                smw[offh + m * WSTR + kp] = *(uint32_t*)&hi2;
                smw[offl + m * WSTR + kp] = *(uint32_t*)&lo2;
            }
        }

        __syncthreads();   // tiles visible

        // ---- MMA phase: 4 k-steps of 16 ----
#pragma unroll
        for (int ks = 0; ks < 4; ks++) {
            const int ksw = ks * 8;
            uint32_t ah[2][4], al[2][4], bh[4][2], bl[4][2];
#pragma unroll
            for (int mt = 0; mt < 2; mt++) {
                int row = wm * 32 + mt * 16 + lr;
                const uint32_t* pa = smw + row * WSTR + ksw + lc;
                ah[mt][0] = pa[OFF_AH];
                ah[mt][1] = pa[OFF_AH + 8 * WSTR];
                ah[mt][2] = pa[OFF_AH + 4];
                ah[mt][3] = pa[OFF_AH + 8 * WSTR + 4];
                al[mt][0] = pa[OFF_AL];
                al[mt][1] = pa[OFF_AL + 8 * WSTR];
                al[mt][2] = pa[OFF_AL + 4];
                al[mt][3] = pa[OFF_AL + 8 * WSTR + 4];
            }
#pragma unroll
            for (int nt = 0; nt < 4; nt++) {
                int nrow = wn * 32 + nt * 8 + lr;
                const uint32_t* pb = smw + nrow * WSTR + ksw + lc;
                bh[nt][0] = pb[OFF_BH];
                bh[nt][1] = pb[OFF_BH + 4];
                bl[nt][0] = pb[OFF_BL];
                bl[nt][1] = pb[OFF_BL + 4];
            }
#pragma unroll
            for (int mt = 0; mt < 2; mt++)
#pragma unroll
                for (int nt = 0; nt < 4; nt++) {
                    float* cc = c[mt][nt];
                    mma_bf16(cc[0], cc[1], cc[2], cc[3],
                             ah[mt][0], ah[mt][1], ah[mt][2], ah[mt][3],
                             bh[nt][0], bh[nt][1]);
                    mma_bf16(cc[0], cc[1], cc[2], cc[3],
                             ah[mt][0], ah[mt][1], ah[mt][2], ah[mt][3],
                             bl[nt][0], bl[nt][1]);
                    mma_bf16(cc[0], cc[1], cc[2], cc[3],
                             al[mt][0], al[mt][1], al[mt][2], al[mt][3],
                             bh[nt][0], bh[nt][1]);
                }
        }

        __syncthreads();   // MMA reads done before next slice's stores
    }

    // ---- epilogue: write C fragments to partial buffer ----
    float* pp = g_part + (size_t)blockIdx.y * (T_SEQ * IN_CH);
#pragma unroll
    for (int mt = 0; mt < 2; mt++) {
#pragma unroll
        for (int nt = 0; nt < 4; nt++) {
            int row0 = wm * 32 + mt * 16 + lr;
            int col = wn * 32 + nt * 8 + lc * 2;
            *(float2*)(pp + (size_t)(t0 + row0) * IN_CH + col) =
                make_float2(c[mt][nt][0], c[mt][nt][1]);
            *(float2*)(pp + (size_t)(t0 + row0 + 8) * IN_CH + col) =
                make_float2(c[mt][nt][2], c[mt][nt][3]);
        }
    }
}

// K1b: ve = sum over 37 chunk partials (deterministic reduce)
__global__ void __launch_bounds__(256) k1_reduce_kernel() {
    int idx = blockIdx.x * blockDim.x + threadIdx.x;   // 0..131071
    float s = 0.f;
#pragma unroll
    for (int c = 0; c < K1_NCHUNK; c++) s += g_part[c * (T_SEQ * IN_CH) + idx];
    g_ve[idx] = s;
}

// ============================================================================
// K2: gx[t][r] = b_ih[r] + sum_k ve[t][k]*w_ih[r][k]
// ============================================================================
__global__ void __launch_bounds__(256) gx_kernel(const float* __restrict__ w_ih,
                                                 const float* __restrict__ b_ih) {
    const int t = blockIdx.x;
    const int w = threadIdx.x >> 5, l = threadIdx.x & 31;
    float4 vv = *(const float4*)(g_ve + t * IN_CH + l * 4);
    for (int rr = 0; rr < 96; rr++) {
        int r = w * 96 + rr;
        float4 wv = *(const float4*)(w_ih + (size_t)r * IN_CH + l * 4);
        float p = vv.x * wv.x + vv.y * wv.y + vv.z * wv.z + vv.w * wv.w;
#pragma unroll
        for (int o = 16; o; o >>= 1) p += __shfl_xor_sync(0xffffffffu, p, o);
        if (l == 0) g_gx[t * G3 + r] = p + b_ih[r];
    }
}

// ============================================================================
// K3: sequential GRU (unchanged from round 6 — proven 860-892us)
// ============================================================================
__device__ __forceinline__ void cluster_sync_() {
    asm volatile("barrier.cluster.arrive.aligned;" ::: "memory");
    asm volatile("barrier.cluster.wait.aligned;" ::: "memory");
}
__device__ __forceinline__ void st_remote_f32(uint32_t laddr, uint32_t peer, float v) {
    uint32_t raddr;
    asm volatile("mapa.shared::cluster.u32 %0, %1, %2;"
                 : "=r"(raddr) : "r"(laddr), "r"(peer));
    asm volatile("st.shared::cluster.f32 [%0], %1;" :: "r"(raddr), "f"(v) : "memory");
}
__device__ __forceinline__ void arrive_remote(uint32_t lbar, uint32_t peer) {
    uint32_t raddr;
    asm volatile("mapa.shared::cluster.u32 %0, %1, %2;"
                 : "=r"(raddr) : "r"(lbar), "r"(peer));
    asm volatile("mbarrier.arrive.release.cluster.shared::cluster.b64 _, [%0];"
                 :: "r"(raddr) : "memory");
}
__device__ __forceinline__ void wait_parity_cl(uint32_t bar, uint32_t par) {
    uint32_t done;
    do {
        asm volatile(
            "{\n\t.reg .pred p;\n\t"
            "mbarrier.try_wait.parity.acquire.cluster.shared::cta.b64 p, [%1], %2, 0x989680;\n\t"
            "selp.b32 %0, 1, 0, p;\n\t}"
            : "=r"(done) : "r"(bar), "r"(par) : "memory");
    } while (!done);
}
__device__ __forceinline__ float tanh_ap(float x) {
    float y;
    asm("tanh.approx.f32 %0, %1;" : "=f"(y) : "f"(x));
    return y;
}
__device__ __forceinline__ float sigmoid_ap(float x) {
    return fmaf(0.5f, tanh_ap(0.5f * x), 0.5f);
}

__global__ __launch_bounds__(256, 1) __cluster_dims__(8, 1, 1)
void gru_kernel(const float* __restrict__ w_hh, const float* __restrict__ b_hh) {
    __shared__ __align__(16) float sh_h[2][256];            // double-buffered h
    __shared__ __align__(8) unsigned long long sh_bar[2];   // full barrier per buf

    const int tid = threadIdx.x;
    const int rank = blockIdx.x;
    const int j = tid >> 3;            // slot 0..31
    const int o = tid & 7;             // k-octant 0..7
    const int slot = rank * 32 + j;    // global h index owned by this group

    unsigned long long wr[16], wz[16], wn[16];
#pragma unroll
    for (int i = 0; i < 16; i++) {
        int k = o * 32 + ((i + 2 * o) & 15) * 2;
        wr[i] = *(const unsigned long long*)(w_hh + (size_t)(slot)*256 + k);
        wz[i] = *(const unsigned long long*)(w_hh + (size_t)(256 + slot) * 256 + k);
        wn[i] = *(const unsigned long long*)(w_hh + (size_t)(512 + slot) * 256 + k);
    }
    const float bhr = b_hh[slot];
    const float bhz = b_hh[256 + slot];
    const float bhn = b_hh[512 + slot];

    sh_h[0][tid] = 0.f;
    sh_h[1][tid] = 0.f;
    uint32_t bbase = (uint32_t)__cvta_generic_to_shared(&sh_bar[0]);
    if (tid == 0) {
        asm volatile("mbarrier.init.shared.b64 [%0], %1;" :: "r"(bbase),     "r"(8) : "memory");
        asm volatile("mbarrier.init.shared.b64 [%0], %1;" :: "r"(bbase + 8), "r"(8) : "memory");
    }
    __syncthreads();
    cluster_sync_();

    for (int t = 0; t < T_SEQ; t++) {
        const int cur = t & 1, nxt = cur ^ 1;

        const float gxr = g_gx[t * G3 + slot];
        const float gxz = g_gx[t * G3 + 256 + slot];
        const float gxn = g_gx[t * G3 + 512 + slot];

        if (t > 0) wait_parity_cl(bbase + 8u * (uint32_t)cur, ((t - 1) >> 1) & 1);

        const float hprev = sh_h[cur][slot];

        unsigned long long ar = 0ull, az = 0ull, an = 0ull;
        {
            const float* hb = &sh_h[cur][0];
#pragma unroll
            for (int i = 0; i < 16; i++) {
                int k = o * 32 + ((i + 2 * o) & 15) * 2;
                unsigned long long hv = *(const unsigned long long*)(hb + k);
                asm("fma.rn.f32x2 %0, %1, %2, %0;" : "+l"(ar) : "l"(wr[i]), "l"(hv));
                asm("fma.rn.f32x2 %0, %1, %2, %0;" : "+l"(az) : "l"(wz[i]), "l"(hv));
                asm("fma.rn.f32x2 %0, %1, %2, %0;" : "+l"(an) : "l"(wn[i]), "l"(hv));
            }
        }
        float pr, pz, pn;
        {
            float lo, hi;
            asm("mov.b64 {%0, %1}, %2;" : "=f"(lo), "=f"(hi) : "l"(ar)); pr = lo + hi;
            asm("mov.b64 {%0, %1}, %2;" : "=f"(lo), "=f"(hi) : "l"(az)); pz = lo + hi;
            asm("mov.b64 {%0, %1}, %2;" : "=f"(lo), "=f"(hi) : "l"(an)); pn = lo + hi;
        }
#pragma unroll
        for (int d = 1; d < 8; d <<= 1) {
            pr += __shfl_xor_sync(0xffffffffu, pr, d);
            pz += __shfl_xor_sync(0xffffffffu, pz, d);
            pn += __shfl_xor_sync(0xffffffffu, pn, d);
        }

        const float r = sigmoid_ap(gxr + pr + bhr);
        const float z = sigmoid_ap(gxz + pz + bhz);
        const float n = tanh_ap(gxn + r * (pn + bhn));
        const float hnew = n + z * (hprev - n);

        if (o == 0) g_hs[t * HID + slot] = hnew;

        if (t < T_SEQ - 1) {
            uint32_t laddr = (uint32_t)__cvta_generic_to_shared(&sh_h[nxt][slot]);
            st_remote_f32(laddr, (uint32_t)o, hnew);
            __syncthreads();
            if (tid < 8) arrive_remote(bbase + 8u * (uint32_t)nxt, (uint32_t)tid);
        }
    }
    cluster_sync_();
}

// ============================================================================
// K4: logits = hs @ w_attn; alpha = softmax(logits); out = alpha @ hs
// ============================================================================
__global__ void __launch_bounds__(1024) attn_kernel(const float* __restrict__ w_attn,
                                                    float* __restrict__ out) {
    __shared__ float s_alpha[1024];
    __shared__ float s_red[1024];
    __shared__ float s_wa[256];
    const int tid = threadIdx.x;
    if (tid < 256) s_wa[tid] = w_attn[tid];
    __syncthreads();

    const int w = tid >> 5, l = tid & 31;
    for (int tt = 0; tt < 32; tt++) {
        int t = w * 32 + tt;
        const float* hr = g_hs + t * HID;
        float p = 0.f;
#pragma unroll
        for (int j = 0; j < 8; j++) p = fmaf(hr[l + 32 * j], s_wa[l + 32 * j], p);
#pragma unroll
        for (int o = 16; o; o >>= 1) p += __shfl_xor_sync(0xffffffffu, p, o);
        if (l == 0) s_alpha[t] = p;
    }
    __syncthreads();

    float v = s_alpha[tid];
    s_red[tid] = v;
    __syncthreads();
    for (int s = 512; s; s >>= 1) {
        if (tid < s) s_red[tid] = fmaxf(s_red[tid], s_red[tid + s]);
        __syncthreads();
    }
    float m = s_red[0];
    __syncthreads();
    float e = __expf(v - m);
    s_red[tid] = e;
    __syncthreads();
    for (int s = 512; s; s >>= 1) {
        if (tid < s) s_red[tid] = s_red[tid] + s_red[tid + s];
        __syncthreads();
    }
    float inv = 1.f / s_red[0];
    __syncthreads();
    s_alpha[tid] = e * inv;
    __syncthreads();

    const int j = tid & 255, seg = tid >> 8;
    float p = 0.f;
    const float* hp = g_hs + (size_t)seg * 256 * HID + j;
    const float* ap = s_alpha + seg * 256;
    for (int t = 0; t < 256; t++) p = fmaf(ap[t], hp[t * HID], p);
    s_red[tid] = p;
    __syncthreads();
    if (tid < 256)
        out[j] = (s_red[j] + s_red[256 + j]) + (s_red[512 + j] + s_red[768 + j]);
}

// ============================================================================
extern "C" void kernel_launch(void* const* d_in, const int* in_sizes, int n_in,
                              void* d_out, int out_size) {
    const float* X = nullptr;
    const float* H = nullptr;
    const float* w_ih = nullptr;
    const float* w_hh = nullptr;
    const float* b_ih = nullptr;
    const float* b_hh = nullptr;
    const float* w_attn = nullptr;
    for (int i = 0; i < n_in; i++) {
        int s = in_sizes[i];
        const float* p = (const float*)d_in[i];
        if (s == N_NODES * IN_CH)      X = p;
        else if (s == N_NODES * T_SEQ) H = p;
        else if (s == G3 * IN_CH)      w_ih = p;
        else if (s == G3 * HID)        w_hh = p;
        else if (s == G3) { if (!b_ih) b_ih = p; else b_hh = p; }
        else if (s == HID)             w_attn = p;
    }
    float* out = (float*)d_out;

    cudaFuncSetAttribute(k1h_kernel, cudaFuncAttributeMaxDynamicSharedMemorySize,
                         K1_SMEM_BYTES);

    k1h_kernel<<<dim3(8, K1_NCHUNK), 512, K1_SMEM_BYTES>>>(H, X);
    k1_reduce_kernel<<<(T_SEQ * IN_CH) / 256, 256>>>();
    gx_kernel<<<T_SEQ, 256>>>(w_ih, b_ih);
    gru_kernel<<<8, 256>>>(w_hh, b_hh);
    attn_kernel<<<1, 1024>>>(w_attn, out);
}

// round 10
// speedup vs baseline: 5.2005x; 1.3975x over previous
#include <cuda_runtime.h>
#include <cuda_bf16.h>
#include <cstdint>
#include <cstddef>

#define N_NODES 100000
#define T_SEQ   1024
#define IN_CH   128
#define HID     256
#define G3      768     // 3*HID gate rows

// ---------------- scratch (device globals; no allocations allowed) ----------
#define K1_NCHUNK 37
#define K1_CHUNK  2752  // 43*64; 37*2752 = 101824 >= 100000 (guarded)
#define NSLICES   43    // K-slices of 64 per chunk

__device__ float g_part[K1_NCHUNK * T_SEQ * IN_CH];  // ~19.4 MB partials
__device__ float g_ve[T_SEQ * IN_CH];                // visit_emb [1024,128]
__device__ float g_gx[T_SEQ * G3];                   // input gates [1024,768]
__device__ float g_hs[T_SEQ * HID];                  // hidden states [1024,256]

// ============================================================================
// K1 (tensor, legacy mma.sync; cp.async staged, swizzled SMEM transpose) —
// unchanged from round 9 (proven).
// ============================================================================
#define WSTR 36                       // words per tile row
#define STG_ROW 128                   // words per staging row (512B)
#define STG_MAT (64 * STG_ROW)        // words per staging matrix (8192)
#define TILE_BASE (4 * STG_MAT)       // staging: [buf][H/X]
#define OFF_AH (TILE_BASE + 0)
#define OFF_AL (TILE_BASE + 128 * WSTR)
#define OFF_BH (TILE_BASE + 256 * WSTR)
#define OFF_BL (TILE_BASE + 384 * WSTR)
#define K1_SMEM_BYTES ((TILE_BASE + 512 * WSTR) * 4)   // 204800 B

__device__ __forceinline__ void mma_bf16(float& c0, float& c1, float& c2, float& c3,
                                         uint32_t a0, uint32_t a1, uint32_t a2,
                                         uint32_t a3, uint32_t b0, uint32_t b1) {
    asm volatile(
        "mma.sync.aligned.m16n8k16.row.col.f32.bf16.bf16.f32 "
        "{%0,%1,%2,%3}, {%4,%5,%6,%7}, {%8,%9}, {%0,%1,%2,%3};"
        : "+f"(c0), "+f"(c1), "+f"(c2), "+f"(c3)
        : "r"(a0), "r"(a1), "r"(a2), "r"(a3), "r"(b0), "r"(b1));
}

__device__ __forceinline__ void k1_issue_slice(const float* __restrict__ H,
                                               const float* __restrict__ X,
                                               int n0s, int t0, int buf,
                                               uint32_t smb, int tid) {
    const uint32_t stH = smb + (uint32_t)((buf * 2 + 0) * STG_MAT) * 4u;
    const uint32_t stX = smb + (uint32_t)((buf * 2 + 1) * STG_MAT) * 4u;
#pragma unroll
    for (int i = 0; i < 4; i++) {
        int ch = tid + i * 512;          // 0..2047
        int r = ch >> 5;                 // staging row 0..63
        int j = ch & 31;                 // 16B chunk within row
        int js = j ^ ((r >> 1) & 7);     // swizzle (low 3 bits)
        uint32_t doff = (uint32_t)(r * 512 + js * 16);
        int n = n0s + r;
        if (n < N_NODES) {
            const float* gH = H + (size_t)n * T_SEQ + t0 + j * 4;
            const float* gX = X + (size_t)n * IN_CH + j * 4;
            asm volatile("cp.async.ca.shared.global [%0], [%1], 16;"
                         :: "r"(stH + doff), "l"(gH));
            asm volatile("cp.async.ca.shared.global [%0], [%1], 16;"
                         :: "r"(stX + doff), "l"(gX));
        } else {
            asm volatile("st.shared.v4.u32 [%0], {%1,%1,%1,%1};"
                         :: "r"(stH + doff), "r"(0u) : "memory");
            asm volatile("st.shared.v4.u32 [%0], {%1,%1,%1,%1};"
                         :: "r"(stX + doff), "r"(0u) : "memory");
        }
    }
}

__global__ void __launch_bounds__(512, 1) k1h_kernel(const float* __restrict__ H,
                                                     const float* __restrict__ X) {
    extern __shared__ uint32_t smw[];
    float* stf = (float*)smw;
    uint32_t smb;
    asm("{ .reg .u64 t; cvta.to.shared.u64 t, %1; cvt.u32.u64 %0, t; }"
        : "=r"(smb) : "l"((const void*)smw));

    const int tid = threadIdx.x;
    const int t0 = blockIdx.x * 128;
    const int n0 = blockIdx.y * K1_CHUNK;

    const int kp = tid & 31;
    const int mg = tid >> 5;
    const int kx = kp & 7;

    const int wid = tid >> 5, lane = tid & 31;
    const int wm = wid >> 2, wn = wid & 3;
    const int lr = lane >> 2, lc = lane & 3;

    float c[2][4][4];
#pragma unroll
    for (int mt = 0; mt < 2; mt++)
#pragma unroll
        for (int nt = 0; nt < 4; nt++)
#pragma unroll
            for (int r = 0; r < 4; r++) c[mt][nt][r] = 0.f;

    k1_issue_slice(H, X, n0, t0, 0, smb, tid);
    asm volatile("cp.async.commit_group;" ::: "memory");

    for (int s = 0; s < NSLICES; s++) {
        const int buf = s & 1;

        if (s + 1 < NSLICES) {
            k1_issue_slice(H, X, n0 + (s + 1) * 64, t0, buf ^ 1, smb, tid);
            asm volatile("cp.async.commit_group;" ::: "memory");
            asm volatile("cp.async.wait_group 1;" ::: "memory");
        } else {
            asm volatile("cp.async.wait_group 0;" ::: "memory");
        }
        __syncthreads();   // staging[buf] visible to all

#pragma unroll
        for (int tsel = 0; tsel < 2; tsel++) {
            const int so = (buf * 2 + tsel) * STG_MAT;
            const int offh = tsel ? OFF_BH : OFF_AH;
            const int offl = tsel ? OFF_BL : OFF_AL;
            const float* r0p = stf + so + (2 * kp) * STG_ROW;
            const float* r1p = stf + so + (2 * kp + 1) * STG_ROW;
            float4 v00 = *(const float4*)(r0p + (((2 * mg)     ^ kx) << 2));
            float4 v01 = *(const float4*)(r0p + (((2 * mg + 1) ^ kx) << 2));
            float4 v10 = *(const float4*)(r1p + (((2 * mg)     ^ kx) << 2));
            float4 v11 = *(const float4*)(r1p + (((2 * mg + 1) ^ kx) << 2));
            const float* e0 = &v00.x;
            const float* f0 = &v01.x;
            const float* e1 = &v10.x;
            const float* f1 = &v11.x;
#pragma unroll
            for (int j = 0; j < 8; j++) {
                float v0 = (j < 4) ? e0[j] : f0[j - 4];
                float v1 = (j < 4) ? e1[j] : f1[j - 4];
                __nv_bfloat162 hi2 = __floats2bfloat162_rn(v0, v1);
                float l0 = v0 - __bfloat162float(hi2.x);
                float l1 = v1 - __bfloat162float(hi2.y);
                __nv_bfloat162 lo2 = __floats2bfloat162_rn(l0, l1);
                int m = mg * 8 + j;
                smw[offh + m * WSTR + kp] = *(uint32_t*)&hi2;
                smw[offl + m * WSTR + kp] = *(uint32_t*)&lo2;
            }
        }

        __syncthreads();   // tiles visible

#pragma unroll
        for (int ks = 0; ks < 4; ks++) {
            const int ksw = ks * 8;
            uint32_t ah[2][4], al[2][4], bh[4][2], bl[4][2];
#pragma unroll
            for (int mt = 0; mt < 2; mt++) {
                int row = wm * 32 + mt * 16 + lr;
                const uint32_t* pa = smw + row * WSTR + ksw + lc;
                ah[mt][0] = pa[OFF_AH];
                ah[mt][1] = pa[OFF_AH + 8 * WSTR];
                ah[mt][2] = pa[OFF_AH + 4];
                ah[mt][3] = pa[OFF_AH + 8 * WSTR + 4];
                al[mt][0] = pa[OFF_AL];
                al[mt][1] = pa[OFF_AL + 8 * WSTR];
                al[mt][2] = pa[OFF_AL + 4];
                al[mt][3] = pa[OFF_AL + 8 * WSTR + 4];
            }
#pragma unroll
            for (int nt = 0; nt < 4; nt++) {
                int nrow = wn * 32 + nt * 8 + lr;
                const uint32_t* pb = smw + nrow * WSTR + ksw + lc;
                bh[nt][0] = pb[OFF_BH];
                bh[nt][1] = pb[OFF_BH + 4];
                bl[nt][0] = pb[OFF_BL];
                bl[nt][1] = pb[OFF_BL + 4];
            }
#pragma unroll
            for (int mt = 0; mt < 2; mt++)
#pragma unroll
                for (int nt = 0; nt < 4; nt++) {
                    float* cc = c[mt][nt];
                    mma_bf16(cc[0], cc[1], cc[2], cc[3],
                             ah[mt][0], ah[mt][1], ah[mt][2], ah[mt][3],
                             bh[nt][0], bh[nt][1]);
                    mma_bf16(cc[0], cc[1], cc[2], cc[3],
                             ah[mt][0], ah[mt][1], ah[mt][2], ah[mt][3],
                             bl[nt][0], bl[nt][1]);
                    mma_bf16(cc[0], cc[1], cc[2], cc[3],
                             al[mt][0], al[mt][1], al[mt][2], al[mt][3],
                             bh[nt][0], bh[nt][1]);
                }
        }

        __syncthreads();   // MMA reads done before next slice's stores
    }

    float* pp = g_part + (size_t)blockIdx.y * (T_SEQ * IN_CH);
#pragma unroll
    for (int mt = 0; mt < 2; mt++) {
#pragma unroll
        for (int nt = 0; nt < 4; nt++) {
            int row0 = wm * 32 + mt * 16 + lr;
            int col = wn * 32 + nt * 8 + lc * 2;
            *(float2*)(pp + (size_t)(t0 + row0) * IN_CH + col) =
                make_float2(c[mt][nt][0], c[mt][nt][1]);
            *(float2*)(pp + (size_t)(t0 + row0 + 8) * IN_CH + col) =
                make_float2(c[mt][nt][2], c[mt][nt][3]);
        }
    }
}

// K1b: ve = sum over 37 chunk partials (deterministic reduce)
__global__ void __launch_bounds__(256) k1_reduce_kernel() {
    int idx = blockIdx.x * blockDim.x + threadIdx.x;   // 0..131071
    float s = 0.f;
#pragma unroll
    for (int c = 0; c < K1_NCHUNK; c++) s += g_part[c * (T_SEQ * IN_CH) + idx];
    g_ve[idx] = s;
}

// ============================================================================
// K2: gx[t][r] = b_ih[r] + sum_k ve[t][k]*w_ih[r][k]
// ============================================================================
__global__ void __launch_bounds__(256) gx_kernel(const float* __restrict__ w_ih,
                                                 const float* __restrict__ b_ih) {
    const int t = blockIdx.x;
    const int w = threadIdx.x >> 5, l = threadIdx.x & 31;
    float4 vv = *(const float4*)(g_ve + t * IN_CH + l * 4);
    for (int rr = 0; rr < 96; rr++) {
        int r = w * 96 + rr;
        float4 wv = *(const float4*)(w_ih + (size_t)r * IN_CH + l * 4);
        float p = vv.x * wv.x + vv.y * wv.y + vv.z * wv.z + vv.w * wv.w;
#pragma unroll
        for (int o = 16; o; o >>= 1) p += __shfl_xor_sync(0xffffffffu, p, o);
        if (l == 0) g_gx[t * G3 + r] = p + b_ih[r];
    }
}

// ============================================================================
// K3: sequential GRU, cluster of 8 CTAs x 256 threads.
// Handshake v3: __syncthreads after matvec-reads (read-completion certificate),
// then ONE fused st.async per thread — data + barrier tx in a single fabric
// transaction (replaces round 6's store -> sync -> 8 remote arrives).
// Receiver arms its own barrier per phase: arrive.expect_tx(1024B), count=1.
// WAR safety: any CTA's step-t send implies ALL its step-t reads of h[cur]
// retired (syncthreads precedes sends); a peer's step-(t+1) writes into
// h[cur] are gated on receiving our step-t bytes. Symmetric for h[nxt].
// ============================================================================
__device__ __forceinline__ void cluster_sync_() {
    asm volatile("barrier.cluster.arrive.aligned;" ::: "memory");
    asm volatile("barrier.cluster.wait.aligned;" ::: "memory");
}
__device__ __forceinline__ void st_async_remote(uint32_t laddr, uint32_t lbar,
                                                uint32_t peer, float v) {
    uint32_t ra, rb;
    asm volatile("mapa.shared::cluster.u32 %0, %1, %2;"
                 : "=r"(ra) : "r"(laddr), "r"(peer));
    asm volatile("mapa.shared::cluster.u32 %0, %1, %2;"
                 : "=r"(rb) : "r"(lbar), "r"(peer));
    asm volatile(
        "st.async.shared::cluster.mbarrier::complete_tx::bytes.u32 [%0], %1, [%2];"
        :: "r"(ra), "r"(__float_as_uint(v)), "r"(rb) : "memory");
}
__device__ __forceinline__ void arm_expect_tx(uint32_t bar, uint32_t bytes) {
    asm volatile("mbarrier.arrive.expect_tx.shared.b64 _, [%0], %1;"
                 :: "r"(bar), "r"(bytes) : "memory");
}
__device__ __forceinline__ void wait_parity_cl(uint32_t bar, uint32_t par) {
    uint32_t done;
    do {
        asm volatile(
            "{\n\t.reg .pred p;\n\t"
            "mbarrier.try_wait.parity.acquire.cluster.shared::cta.b64 p, [%1], %2, 0x989680;\n\t"
            "selp.b32 %0, 1, 0, p;\n\t}"
            : "=r"(done) : "r"(bar), "r"(par) : "memory");
    } while (!done);
}
__device__ __forceinline__ float tanh_ap(float x) {
    float y;
    asm("tanh.approx.f32 %0, %1;" : "=f"(y) : "f"(x));
    return y;
}
__device__ __forceinline__ float sigmoid_ap(float x) {
    return fmaf(0.5f, tanh_ap(0.5f * x), 0.5f);
}

__global__ __launch_bounds__(256, 1) __cluster_dims__(8, 1, 1)
void gru_kernel(const float* __restrict__ w_hh, const float* __restrict__ b_hh) {
    __shared__ __align__(16) float sh_h[2][256];            // double-buffered h
    __shared__ __align__(8) unsigned long long sh_bar[2];   // full barrier per buf

    const int tid = threadIdx.x;
    const int rank = blockIdx.x;
    const int j = tid >> 3;            // slot 0..31
    const int o = tid & 7;             // k-octant 0..7
    const int slot = rank * 32 + j;    // global h index owned by this group

    unsigned long long wr[16], wz[16], wn[16];
#pragma unroll
    for (int i = 0; i < 16; i++) {
        int k = o * 32 + ((i + 2 * o) & 15) * 2;
        wr[i] = *(const unsigned long long*)(w_hh + (size_t)(slot)*256 + k);
        wz[i] = *(const unsigned long long*)(w_hh + (size_t)(256 + slot) * 256 + k);
        wn[i] = *(const unsigned long long*)(w_hh + (size_t)(512 + slot) * 256 + k);
    }
    const float bhr = b_hh[slot];
    const float bhz = b_hh[256 + slot];
    const float bhn = b_hh[512 + slot];

    sh_h[0][tid] = 0.f;
    sh_h[1][tid] = 0.f;
    uint32_t bbase = (uint32_t)__cvta_generic_to_shared(&sh_bar[0]);
    if (tid == 0) {
        asm volatile("mbarrier.init.shared.b64 [%0], %1;" :: "r"(bbase),     "r"(1) : "memory");
        asm volatile("mbarrier.init.shared.b64 [%0], %1;" :: "r"(bbase + 8), "r"(1) : "memory");
        arm_expect_tx(bbase, 1024u);       // buffer-0 stores (written at step 1)
        arm_expect_tx(bbase + 8, 1024u);   // buffer-1 stores (written at step 0)
    }
    __syncthreads();
    cluster_sync_();   // barriers + h0 visible cluster-wide

    for (int t = 0; t < T_SEQ; t++) {
        const int cur = t & 1, nxt = cur ^ 1;

        // gx loads (h-independent) issued before the wait to hide latency
        const float gxr = g_gx[t * G3 + slot];
        const float gxz = g_gx[t * G3 + 256 + slot];
        const float gxn = g_gx[t * G3 + 512 + slot];

        if (t > 0) {
            wait_parity_cl(bbase + 8u * (uint32_t)cur, ((t - 1) >> 1) & 1);
            if (tid == 0) arm_expect_tx(bbase + 8u * (uint32_t)cur, 1024u);
        }

        const float hprev = sh_h[cur][slot];

        unsigned long long ar = 0ull, az = 0ull, an = 0ull;
        {
            const float* hb = &sh_h[cur][0];
#pragma unroll
            for (int i = 0; i < 16; i++) {
                int k = o * 32 + ((i + 2 * o) & 15) * 2;
                unsigned long long hv = *(const unsigned long long*)(hb + k);
                asm("fma.rn.f32x2 %0, %1, %2, %0;" : "+l"(ar) : "l"(wr[i]), "l"(hv));
                asm("fma.rn.f32x2 %0, %1, %2, %0;" : "+l"(az) : "l"(wz[i]), "l"(hv));
                asm("fma.rn.f32x2 %0, %1, %2, %0;" : "+l"(an) : "l"(wn[i]), "l"(hv));
            }
        }
        float pr, pz, pn;
        {
            float lo, hi;
            asm("mov.b64 {%0, %1}, %2;" : "=f"(lo), "=f"(hi) : "l"(ar)); pr = lo + hi;
            asm("mov.b64 {%0, %1}, %2;" : "=f"(lo), "=f"(hi) : "l"(az)); pz = lo + hi;
            asm("mov.b64 {%0, %1}, %2;" : "=f"(lo), "=f"(hi) : "l"(an)); pn = lo + hi;
        }

        // all reads of sh_h[cur] are complete here: certify before the sends
        if (t < T_SEQ - 1) __syncthreads();

#pragma unroll
        for (int d = 1; d < 8; d <<= 1) {
            pr += __shfl_xor_sync(0xffffffffu, pr, d);
            pz += __shfl_xor_sync(0xffffffffu, pz, d);
            pn += __shfl_xor_sync(0xffffffffu, pn, d);
        }

        const float r = sigmoid_ap(gxr + pr + bhr);
        const float z = sigmoid_ap(gxz + pz + bhz);
        const float n = tanh_ap(gxn + r * (pn + bhn));
        const float hnew = n + z * (hprev - n);

        if (t < T_SEQ - 1) {
            // one fused data+signal transaction per thread, to peer o
            uint32_t laddr = (uint32_t)__cvta_generic_to_shared(&sh_h[nxt][slot]);
            st_async_remote(laddr, bbase + 8u * (uint32_t)nxt, (uint32_t)o, hnew);
        }
        if (o == 0) g_hs[t * HID + slot] = hnew;
    }
    cluster_sync_();   // drain in-flight traffic before exit
}

// ============================================================================
// K4: logits = hs @ w_attn; alpha = softmax(logits); out = alpha @ hs
// ============================================================================
__global__ void __launch_bounds__(1024) attn_kernel(const float* __restrict__ w_attn,
                                                    float* __restrict__ out) {
    __shared__ float s_alpha[1024];
    __shared__ float s_red[1024];
    __shared__ float s_wa[256];
    const int tid = threadIdx.x;
    if (tid < 256) s_wa[tid] = w_attn[tid];
    __syncthreads();

    const int w = tid >> 5, l = tid & 31;
    for (int tt = 0; tt < 32; tt++) {
        int t = w * 32 + tt;
        const float* hr = g_hs + t * HID;
        float p = 0.f;
#pragma unroll
        for (int j = 0; j < 8; j++) p = fmaf(hr[l + 32 * j], s_wa[l + 32 * j], p);
#pragma unroll
        for (int o = 16; o; o >>= 1) p += __shfl_xor_sync(0xffffffffu, p, o);
        if (l == 0) s_alpha[t] = p;
    }
    __syncthreads();

    float v = s_alpha[tid];
    s_red[tid] = v;
    __syncthreads();
    for (int s = 512; s; s >>= 1) {
        if (tid < s) s_red[tid] = fmaxf(s_red[tid], s_red[tid + s]);
        __syncthreads();
    }
    float m = s_red[0];
    __syncthreads();
    float e = __expf(v - m);
    s_red[tid] = e;
    __syncthreads();
    for (int s = 512; s; s >>= 1) {
        if (tid < s) s_red[tid] = s_red[tid] + s_red[tid + s];
        __syncthreads();
    }
    float inv = 1.f / s_red[0];
    __syncthreads();
    s_alpha[tid] = e * inv;
    __syncthreads();

    const int j = tid & 255, seg = tid >> 8;
    float p = 0.f;
    const float* hp = g_hs + (size_t)seg * 256 * HID + j;
    const float* ap = s_alpha + seg * 256;
    for (int t = 0; t < 256; t++) p = fmaf(ap[t], hp[t * HID], p);
    s_red[tid] = p;
    __syncthreads();
    if (tid < 256)
        out[j] = (s_red[j] + s_red[256 + j]) + (s_red[512 + j] + s_red[768 + j]);
}

// ============================================================================
extern "C" void kernel_launch(void* const* d_in, const int* in_sizes, int n_in,
                              void* d_out, int out_size) {
    const float* X = nullptr;
    const float* H = nullptr;
    const float* w_ih = nullptr;
    const float* w_hh = nullptr;
    const float* b_ih = nullptr;
    const float* b_hh = nullptr;
    const float* w_attn = nullptr;
    for (int i = 0; i < n_in; i++) {
        int s = in_sizes[i];
        const float* p = (const float*)d_in[i];
        if (s == N_NODES * IN_CH)      X = p;
        else if (s == N_NODES * T_SEQ) H = p;
        else if (s == G3 * IN_CH)      w_ih = p;
        else if (s == G3 * HID)        w_hh = p;
        else if (s == G3) { if (!b_ih) b_ih = p; else b_hh = p; }
        else if (s == HID)             w_attn = p;
    }
    float* out = (float*)d_out;

    cudaFuncSetAttribute(k1h_kernel, cudaFuncAttributeMaxDynamicSharedMemorySize,
                         K1_SMEM_BYTES);

    k1h_kernel<<<dim3(8, K1_NCHUNK), 512, K1_SMEM_BYTES>>>(H, X);
    k1_reduce_kernel<<<(T_SEQ * IN_CH) / 256, 256>>>();
    gx_kernel<<<T_SEQ, 256>>>(w_ih, b_ih);
    gru_kernel<<<8, 256>>>(w_hh, b_hh);
    attn_kernel<<<1, 1024>>>(w_attn, out);
}

// round 11
// speedup vs baseline: 5.3281x; 1.0245x over previous
#include <cuda_runtime.h>
#include <cuda_bf16.h>
#include <cstdint>
#include <cstddef>

#define N_NODES 100000
#define T_SEQ   1024
#define IN_CH   128
#define HID     256
#define G3      768     // 3*HID gate rows

// ---------------- scratch (device globals; no allocations allowed) ----------
#define K1_NCHUNK 37
#define K1_CHUNK  2752  // 43*64; 37*2752 = 101824 >= 100000 (guarded)
#define NSLICES   43    // K-slices of 64 per chunk

__device__ float g_part[K1_NCHUNK * T_SEQ * IN_CH];  // ~19.4 MB partials
__device__ float g_ve[T_SEQ * IN_CH];                // visit_emb [1024,128]
__device__ float g_gx[T_SEQ * G3];                   // input gates [1024,768]
__device__ float g_hs[T_SEQ * HID];                  // hidden states [1024,256]

// ============================================================================
// K1 (tensor, legacy mma.sync; cp.async staged, swizzled SMEM transpose) —
// unchanged from round 9/10 (proven).
// ============================================================================
#define WSTR 36                       // words per tile row
#define STG_ROW 128                   // words per staging row (512B)
#define STG_MAT (64 * STG_ROW)        // words per staging matrix (8192)
#define TILE_BASE (4 * STG_MAT)       // staging: [buf][H/X]
#define OFF_AH (TILE_BASE + 0)
#define OFF_AL (TILE_BASE + 128 * WSTR)
#define OFF_BH (TILE_BASE + 256 * WSTR)
#define OFF_BL (TILE_BASE + 384 * WSTR)
#define K1_SMEM_BYTES ((TILE_BASE + 512 * WSTR) * 4)   // 204800 B

__device__ __forceinline__ void mma_bf16(float& c0, float& c1, float& c2, float& c3,
                                         uint32_t a0, uint32_t a1, uint32_t a2,
                                         uint32_t a3, uint32_t b0, uint32_t b1) {
    asm volatile(
        "mma.sync.aligned.m16n8k16.row.col.f32.bf16.bf16.f32 "
        "{%0,%1,%2,%3}, {%4,%5,%6,%7}, {%8,%9}, {%0,%1,%2,%3};"
        : "+f"(c0), "+f"(c1), "+f"(c2), "+f"(c3)
        : "r"(a0), "r"(a1), "r"(a2), "r"(a3), "r"(b0), "r"(b1));
}

__device__ __forceinline__ void k1_issue_slice(const float* __restrict__ H,
                                               const float* __restrict__ X,
                                               int n0s, int t0, int buf,
                                               uint32_t smb, int tid) {
    const uint32_t stH = smb + (uint32_t)((buf * 2 + 0) * STG_MAT) * 4u;
    const uint32_t stX = smb + (uint32_t)((buf * 2 + 1) * STG_MAT) * 4u;
#pragma unroll
    for (int i = 0; i < 4; i++) {
        int ch = tid + i * 512;          // 0..2047
        int r = ch >> 5;                 // staging row 0..63
        int j = ch & 31;                 // 16B chunk within row
        int js = j ^ ((r >> 1) & 7);     // swizzle (low 3 bits)
        uint32_t doff = (uint32_t)(r * 512 + js * 16);
        int n = n0s + r;
        if (n < N_NODES) {
            const float* gH = H + (size_t)n * T_SEQ + t0 + j * 4;
            const float* gX = X + (size_t)n * IN_CH + j * 4;
            asm volatile("cp.async.ca.shared.global [%0], [%1], 16;"
                         :: "r"(stH + doff), "l"(gH));
            asm volatile("cp.async.ca.shared.global [%0], [%1], 16;"
                         :: "r"(stX + doff), "l"(gX));
        } else {
            asm volatile("st.shared.v4.u32 [%0], {%1,%1,%1,%1};"
                         :: "r"(stH + doff), "r"(0u) : "memory");
            asm volatile("st.shared.v4.u32 [%0], {%1,%1,%1,%1};"
                         :: "r"(stX + doff), "r"(0u) : "memory");
        }
    }
}

__global__ void __launch_bounds__(512, 1) k1h_kernel(const float* __restrict__ H,
                                                     const float* __restrict__ X) {
    extern __shared__ uint32_t smw[];
    float* stf = (float*)smw;
    uint32_t smb;
    asm("{ .reg .u64 t; cvta.to.shared.u64 t, %1; cvt.u32.u64 %0, t; }"
        : "=r"(smb) : "l"((const void*)smw));

    const int tid = threadIdx.x;
    const int t0 = blockIdx.x * 128;
    const int n0 = blockIdx.y * K1_CHUNK;

    const int kp = tid & 31;
    const int mg = tid >> 5;
    const int kx = kp & 7;

    const int wid = tid >> 5, lane = tid & 31;
    const int wm = wid >> 2, wn = wid & 3;
    const int lr = lane >> 2, lc = lane & 3;

    float c[2][4][4];
#pragma unroll
    for (int mt = 0; mt < 2; mt++)
#pragma unroll
        for (int nt = 0; nt < 4; nt++)
#pragma unroll
            for (int r = 0; r < 4; r++) c[mt][nt][r] = 0.f;

    k1_issue_slice(H, X, n0, t0, 0, smb, tid);
    asm volatile("cp.async.commit_group;" ::: "memory");

    for (int s = 0; s < NSLICES; s++) {
        const int buf = s & 1;

        if (s + 1 < NSLICES) {
            k1_issue_slice(H, X, n0 + (s + 1) * 64, t0, buf ^ 1, smb, tid);
            asm volatile("cp.async.commit_group;" ::: "memory");
            asm volatile("cp.async.wait_group 1;" ::: "memory");
        } else {
            asm volatile("cp.async.wait_group 0;" ::: "memory");
        }
        __syncthreads();   // staging[buf] visible to all

#pragma unroll
        for (int tsel = 0; tsel < 2; tsel++) {
            const int so = (buf * 2 + tsel) * STG_MAT;
            const int offh = tsel ? OFF_BH : OFF_AH;
            const int offl = tsel ? OFF_BL : OFF_AL;
            const float* r0p = stf + so + (2 * kp) * STG_ROW;
            const float* r1p = stf + so + (2 * kp + 1) * STG_ROW;
            float4 v00 = *(const float4*)(r0p + (((2 * mg)     ^ kx) << 2));
            float4 v01 = *(const float4*)(r0p + (((2 * mg + 1) ^ kx) << 2));
            float4 v10 = *(const float4*)(r1p + (((2 * mg)     ^ kx) << 2));
            float4 v11 = *(const float4*)(r1p + (((2 * mg + 1) ^ kx) << 2));
            const float* e0 = &v00.x;
            const float* f0 = &v01.x;
            const float* e1 = &v10.x;
            const float* f1 = &v11.x;
#pragma unroll
            for (int j = 0; j < 8; j++) {
                float v0 = (j < 4) ? e0[j] : f0[j - 4];
                float v1 = (j < 4) ? e1[j] : f1[j - 4];
                __nv_bfloat162 hi2 = __floats2bfloat162_rn(v0, v1);
                float l0 = v0 - __bfloat162float(hi2.x);
                float l1 = v1 - __bfloat162float(hi2.y);
                __nv_bfloat162 lo2 = __floats2bfloat162_rn(l0, l1);
                int m = mg * 8 + j;
                smw[offh + m * WSTR + kp] = *(uint32_t*)&hi2;
                smw[offl + m * WSTR + kp] = *(uint32_t*)&lo2;
            }
        }

        __syncthreads();   // tiles visible

#pragma unroll
        for (int ks = 0; ks < 4; ks++) {
            const int ksw = ks * 8;
            uint32_t ah[2][4], al[2][4], bh[4][2], bl[4][2];
#pragma unroll
            for (int mt = 0; mt < 2; mt++) {
                int row = wm * 32 + mt * 16 + lr;
                const uint32_t* pa = smw + row * WSTR + ksw + lc;
                ah[mt][0] = pa[OFF_AH];
                ah[mt][1] = pa[OFF_AH + 8 * WSTR];
                ah[mt][2] = pa[OFF_AH + 4];
                ah[mt][3] = pa[OFF_AH + 8 * WSTR + 4];
                al[mt][0] = pa[OFF_AL];
                al[mt][1] = pa[OFF_AL + 8 * WSTR];
                al[mt][2] = pa[OFF_AL + 4];
                al[mt][3] = pa[OFF_AL + 8 * WSTR + 4];
            }
#pragma unroll
            for (int nt = 0; nt < 4; nt++) {
                int nrow = wn * 32 + nt * 8 + lr;
                const uint32_t* pb = smw + nrow * WSTR + ksw + lc;
                bh[nt][0] = pb[OFF_BH];
                bh[nt][1] = pb[OFF_BH + 4];
                bl[nt][0] = pb[OFF_BL];
                bl[nt][1] = pb[OFF_BL + 4];
            }
#pragma unroll
            for (int mt = 0; mt < 2; mt++)
#pragma unroll
                for (int nt = 0; nt < 4; nt++) {
                    float* cc = c[mt][nt];
                    mma_bf16(cc[0], cc[1], cc[2], cc[3],
                             ah[mt][0], ah[mt][1], ah[mt][2], ah[mt][3],
                             bh[nt][0], bh[nt][1]);
                    mma_bf16(cc[0], cc[1], cc[2], cc[3],
                             ah[mt][0], ah[mt][1], ah[mt][2], ah[mt][3],
                             bl[nt][0], bl[nt][1]);
                    mma_bf16(cc[0], cc[1], cc[2], cc[3],
                             al[mt][0], al[mt][1], al[mt][2], al[mt][3],
                             bh[nt][0], bh[nt][1]);
                }
        }

        __syncthreads();   // MMA reads done before next slice's stores
    }

    float* pp = g_part + (size_t)blockIdx.y * (T_SEQ * IN_CH);
#pragma unroll
    for (int mt = 0; mt < 2; mt++) {
#pragma unroll
        for (int nt = 0; nt < 4; nt++) {
            int row0 = wm * 32 + mt * 16 + lr;
            int col = wn * 32 + nt * 8 + lc * 2;
            *(float2*)(pp + (size_t)(t0 + row0) * IN_CH + col) =
                make_float2(c[mt][nt][0], c[mt][nt][1]);
            *(float2*)(pp + (size_t)(t0 + row0 + 8) * IN_CH + col) =
                make_float2(c[mt][nt][2], c[mt][nt][3]);
        }
    }
}

// K1b: ve = sum over 37 chunk partials (deterministic reduce)
__global__ void __launch_bounds__(256) k1_reduce_kernel() {
    int idx = blockIdx.x * blockDim.x + threadIdx.x;   // 0..131071
    float s = 0.f;
#pragma unroll
    for (int c = 0; c < K1_NCHUNK; c++) s += g_part[c * (T_SEQ * IN_CH) + idx];
    g_ve[idx] = s;
}

// ============================================================================
// K2: gx[t][r] = b_ih[r] + sum_k ve[t][k]*w_ih[r][k]
// ============================================================================
__global__ void __launch_bounds__(256) gx_kernel(const float* __restrict__ w_ih,
                                                 const float* __restrict__ b_ih) {
    const int t = blockIdx.x;
    const int w = threadIdx.x >> 5, l = threadIdx.x & 31;
    float4 vv = *(const float4*)(g_ve + t * IN_CH + l * 4);
    for (int rr = 0; rr < 96; rr++) {
        int r = w * 96 + rr;
        float4 wv = *(const float4*)(w_ih + (size_t)r * IN_CH + l * 4);
        float p = vv.x * wv.x + vv.y * wv.y + vv.z * wv.z + vv.w * wv.w;
#pragma unroll
        for (int o = 16; o; o >>= 1) p += __shfl_xor_sync(0xffffffffu, p, o);
        if (l == 0) g_gx[t * G3 + r] = p + b_ih[r];
    }
}

// ============================================================================
// K3: sequential GRU, cluster of SIXTEEN CTAs x 128 threads (non-portable
// cluster size; runtime cluster attr). Per CTA: 16 slots x 3 gates = 48 rows
// -> half the per-SMSP FMA issue of the 8-CTA version. Same fused st.async
// handshake; each thread sends its slot's hnew to peers o and o+8.
// WAR safety as round 10 (syncthreads-before-sends certificate).
// ============================================================================
#define GRU_NCTA 16
__device__ __forceinline__ void cluster_sync_() {
    asm volatile("barrier.cluster.arrive.aligned;" ::: "memory");
    asm volatile("barrier.cluster.wait.aligned;" ::: "memory");
}
__device__ __forceinline__ void st_async_remote(uint32_t laddr, uint32_t lbar,
                                                uint32_t peer, float v) {
    uint32_t ra, rb;
    asm volatile("mapa.shared::cluster.u32 %0, %1, %2;"
                 : "=r"(ra) : "r"(laddr), "r"(peer));
    asm volatile("mapa.shared::cluster.u32 %0, %1, %2;"
                 : "=r"(rb) : "r"(lbar), "r"(peer));
    asm volatile(
        "st.async.shared::cluster.mbarrier::complete_tx::bytes.u32 [%0], %1, [%2];"
        :: "r"(ra), "r"(__float_as_uint(v)), "r"(rb) : "memory");
}
__device__ __forceinline__ void arm_expect_tx(uint32_t bar, uint32_t bytes) {
    asm volatile("mbarrier.arrive.expect_tx.shared.b64 _, [%0], %1;"
                 :: "r"(bar), "r"(bytes) : "memory");
}
__device__ __forceinline__ void wait_parity_cl(uint32_t bar, uint32_t par) {
    uint32_t done;
    do {
        asm volatile(
            "{\n\t.reg .pred p;\n\t"
            "mbarrier.try_wait.parity.acquire.cluster.shared::cta.b64 p, [%1], %2, 0x989680;\n\t"
            "selp.b32 %0, 1, 0, p;\n\t}"
            : "=r"(done) : "r"(bar), "r"(par) : "memory");
    } while (!done);
}
__device__ __forceinline__ float tanh_ap(float x) {
    float y;
    asm("tanh.approx.f32 %0, %1;" : "=f"(y) : "f"(x));
    return y;
}
__device__ __forceinline__ float sigmoid_ap(float x) {
    return fmaf(0.5f, tanh_ap(0.5f * x), 0.5f);
}

__global__ void __launch_bounds__(128, 1)
gru_kernel(const float* __restrict__ w_hh, const float* __restrict__ b_hh) {
    __shared__ __align__(16) float sh_h[2][256];            // double-buffered h
    __shared__ __align__(8) unsigned long long sh_bar[2];   // full barrier per buf

    const int tid = threadIdx.x;
    const int rank = blockIdx.x;       // 0..15
    const int j = tid >> 3;            // slot 0..15
    const int o = tid & 7;             // k-octant 0..7
    const int slot = rank * 16 + j;    // global h index owned by this group

    unsigned long long wr[16], wz[16], wn[16];
#pragma unroll
    for (int i = 0; i < 16; i++) {
        int k = o * 32 + ((i + 2 * o) & 15) * 2;
        wr[i] = *(const unsigned long long*)(w_hh + (size_t)(slot)*256 + k);
        wz[i] = *(const unsigned long long*)(w_hh + (size_t)(256 + slot) * 256 + k);
        wn[i] = *(const unsigned long long*)(w_hh + (size_t)(512 + slot) * 256 + k);
    }
    const float bhr = b_hh[slot];
    const float bhz = b_hh[256 + slot];
    const float bhn = b_hh[512 + slot];

    sh_h[0][tid] = 0.f;   sh_h[0][tid + 128] = 0.f;
    sh_h[1][tid] = 0.f;   sh_h[1][tid + 128] = 0.f;
    uint32_t bbase = (uint32_t)__cvta_generic_to_shared(&sh_bar[0]);
    if (tid == 0) {
        asm volatile("mbarrier.init.shared.b64 [%0], %1;" :: "r"(bbase),     "r"(1) : "memory");
        asm volatile("mbarrier.init.shared.b64 [%0], %1;" :: "r"(bbase + 8), "r"(1) : "memory");
        arm_expect_tx(bbase, 1024u);       // buffer-0 stores (written at step 1)
        arm_expect_tx(bbase + 8, 1024u);   // buffer-1 stores (written at step 0)
    }
    __syncthreads();
    cluster_sync_();   // barriers + h0 visible cluster-wide

    for (int t = 0; t < T_SEQ; t++) {
        const int cur = t & 1, nxt = cur ^ 1;

        // gx loads (h-independent) issued before the wait to hide latency
        const float gxr = g_gx[t * G3 + slot];
        const float gxz = g_gx[t * G3 + 256 + slot];
        const float gxn = g_gx[t * G3 + 512 + slot];

        if (t > 0) {
            wait_parity_cl(bbase + 8u * (uint32_t)cur, ((t - 1) >> 1) & 1);
            if (tid == 0) arm_expect_tx(bbase + 8u * (uint32_t)cur, 1024u);
        }

        const float hprev = sh_h[cur][slot];

        unsigned long long ar = 0ull, az = 0ull, an = 0ull;
        {
            const float* hb = &sh_h[cur][0];
#pragma unroll
            for (int i = 0; i < 16; i++) {
                int k = o * 32 + ((i + 2 * o) & 15) * 2;
                unsigned long long hv = *(const unsigned long long*)(hb + k);
                asm("fma.rn.f32x2 %0, %1, %2, %0;" : "+l"(ar) : "l"(wr[i]), "l"(hv));
                asm("fma.rn.f32x2 %0, %1, %2, %0;" : "+l"(az) : "l"(wz[i]), "l"(hv));
                asm("fma.rn.f32x2 %0, %1, %2, %0;" : "+l"(an) : "l"(wn[i]), "l"(hv));
            }
        }
        float pr, pz, pn;
        {
            float lo, hi;
            asm("mov.b64 {%0, %1}, %2;" : "=f"(lo), "=f"(hi) : "l"(ar)); pr = lo + hi;
            asm("mov.b64 {%0, %1}, %2;" : "=f"(lo), "=f"(hi) : "l"(az)); pz = lo + hi;
            asm("mov.b64 {%0, %1}, %2;" : "=f"(lo), "=f"(hi) : "l"(an)); pn = lo + hi;
        }

        // all reads of sh_h[cur] complete here: certify before the sends
        if (t < T_SEQ - 1) __syncthreads();

#pragma unroll
        for (int d = 1; d < 8; d <<= 1) {
            pr += __shfl_xor_sync(0xffffffffu, pr, d);
            pz += __shfl_xor_sync(0xffffffffu, pz, d);
            pn += __shfl_xor_sync(0xffffffffu, pn, d);
        }

        const float r = sigmoid_ap(gxr + pr + bhr);
        const float z = sigmoid_ap(gxz + pz + bhz);
        const float n = tanh_ap(gxn + r * (pn + bhn));
        const float hnew = n + z * (hprev - n);

        if (t < T_SEQ - 1) {
            // fused data+signal transactions, to peers o and o+8
            uint32_t laddr = (uint32_t)__cvta_generic_to_shared(&sh_h[nxt][slot]);
            st_async_remote(laddr, bbase + 8u * (uint32_t)nxt, (uint32_t)o, hnew);
            st_async_remote(laddr, bbase + 8u * (uint32_t)nxt, (uint32_t)(o + 8), hnew);
        }
        if (o == 0) g_hs[t * HID + slot] = hnew;
    }
    cluster_sync_();   // drain in-flight traffic before exit
}

// ============================================================================
// K4: logits = hs @ w_attn; alpha = softmax(logits); out = alpha @ hs
// ============================================================================
__global__ void __launch_bounds__(1024) attn_kernel(const float* __restrict__ w_attn,
                                                    float* __restrict__ out) {
    __shared__ float s_alpha[1024];
    __shared__ float s_red[1024];
    __shared__ float s_wa[256];
    const int tid = threadIdx.x;
    if (tid < 256) s_wa[tid] = w_attn[tid];
    __syncthreads();

    const int w = tid >> 5, l = tid & 31;
    for (int tt = 0; tt < 32; tt++) {
        int t = w * 32 + tt;
        const float* hr = g_hs + t * HID;
        float p = 0.f;
#pragma unroll
        for (int j = 0; j < 8; j++) p = fmaf(hr[l + 32 * j], s_wa[l + 32 * j], p);
#pragma unroll
        for (int o = 16; o; o >>= 1) p += __shfl_xor_sync(0xffffffffu, p, o);
        if (l == 0) s_alpha[t] = p;
    }
    __syncthreads();

    float v = s_alpha[tid];
    s_red[tid] = v;
    __syncthreads();
    for (int s = 512; s; s >>= 1) {
        if (tid < s) s_red[tid] = fmaxf(s_red[tid], s_red[tid + s]);
        __syncthreads();
    }
    float m = s_red[0];
    __syncthreads();
    float e = __expf(v - m);
    s_red[tid] = e;
    __syncthreads();
    for (int s = 512; s; s >>= 1) {
        if (tid < s) s_red[tid] = s_red[tid] + s_red[tid + s];
        __syncthreads();
    }
    float inv = 1.f / s_red[0];
    __syncthreads();
    s_alpha[tid] = e * inv;
    __syncthreads();

    const int j = tid & 255, seg = tid >> 8;
    float p = 0.f;
    const float* hp = g_hs + (size_t)seg * 256 * HID + j;
    const float* ap = s_alpha + seg * 256;
    for (int t = 0; t < 256; t++) p = fmaf(ap[t], hp[t * HID], p);
    s_red[tid] = p;
    __syncthreads();
    if (tid < 256)
        out[j] = (s_red[j] + s_red[256 + j]) + (s_red[512 + j] + s_red[768 + j]);
}

// ============================================================================
extern "C" void kernel_launch(void* const* d_in, const int* in_sizes, int n_in,
                              void* d_out, int out_size) {
    const float* X = nullptr;
    const float* H = nullptr;
    const float* w_ih = nullptr;
    const float* w_hh = nullptr;
    const float* b_ih = nullptr;
    const float* b_hh = nullptr;
    const float* w_attn = nullptr;
    for (int i = 0; i < n_in; i++) {
        int s = in_sizes[i];
        const float* p = (const float*)d_in[i];
        if (s == N_NODES * IN_CH)      X = p;
        else if (s == N_NODES * T_SEQ) H = p;
        else if (s == G3 * IN_CH)      w_ih = p;
        else if (s == G3 * HID)        w_hh = p;
        else if (s == G3) { if (!b_ih) b_ih = p; else b_hh = p; }
        else if (s == HID)             w_attn = p;
    }
    float* out = (float*)d_out;

    cudaFuncSetAttribute(k1h_kernel, cudaFuncAttributeMaxDynamicSharedMemorySize,
                         K1_SMEM_BYTES);

    k1h_kernel<<<dim3(8, K1_NCHUNK), 512, K1_SMEM_BYTES>>>(H, X);
    k1_reduce_kernel<<<(T_SEQ * IN_CH) / 256, 256>>>();
    gx_kernel<<<T_SEQ, 256>>>(w_ih, b_ih);

    // GRU: 16-CTA cluster (non-portable size), runtime cluster attribute
    cudaFuncSetAttribute(gru_kernel,
                         cudaFuncAttributeNonPortableClusterSizeAllowed, 1);
    {
        cudaLaunchConfig_t cfg = {};
        cfg.gridDim = dim3(GRU_NCTA, 1, 1);
        cfg.blockDim = dim3(128, 1, 1);
        cfg.dynamicSmemBytes = 0;
        cudaLaunchAttribute attrs[1];
        attrs[0].id = cudaLaunchAttributeClusterDimension;
        attrs[0].val.clusterDim = {GRU_NCTA, 1, 1};
        cfg.attrs = attrs;
        cfg.numAttrs = 1;
        cudaLaunchKernelEx(&cfg, gru_kernel, w_hh, b_hh);
    }

    attn_kernel<<<1, 1024>>>(w_attn, out);
}

// round 12
// speedup vs baseline: 5.5042x; 1.0331x over previous
#include <cuda_runtime.h>
#include <cuda_bf16.h>
#include <cstdint>
#include <cstddef>

#define N_NODES 100000
#define T_SEQ   1024
#define IN_CH   128
#define HID     256
#define G3      768     // 3*HID gate rows

// ---------------- scratch (device globals; no allocations allowed) ----------
#define K1_NCHUNK 37
#define K1_CHUNK  2752  // 43*64; 37*2752 = 101824 >= 100000 (guarded)
#define NSLICES   43    // K-slices of 64 per chunk

__device__ float g_part[K1_NCHUNK * T_SEQ * IN_CH];  // ~19.4 MB partials
__device__ float g_ve[T_SEQ * IN_CH];                // visit_emb [1024,128]
__device__ float g_gx[T_SEQ * G3];                   // input gates [1024,768]
__device__ float g_hs[T_SEQ * HID];                  // hidden states [1024,256]

// ============================================================================
// K1 (tensor, legacy mma.sync; cp.async staged, swizzled SMEM transpose) —
// unchanged from rounds 9-11 (proven).
// ============================================================================
#define WSTR 36                       // words per tile row
#define STG_ROW 128                   // words per staging row (512B)
#define STG_MAT (64 * STG_ROW)        // words per staging matrix (8192)
#define TILE_BASE (4 * STG_MAT)       // staging: [buf][H/X]
#define OFF_AH (TILE_BASE + 0)
#define OFF_AL (TILE_BASE + 128 * WSTR)
#define OFF_BH (TILE_BASE + 256 * WSTR)
#define OFF_BL (TILE_BASE + 384 * WSTR)
#define K1_SMEM_BYTES ((TILE_BASE + 512 * WSTR) * 4)   // 204800 B

__device__ __forceinline__ void mma_bf16(float& c0, float& c1, float& c2, float& c3,
                                         uint32_t a0, uint32_t a1, uint32_t a2,
                                         uint32_t a3, uint32_t b0, uint32_t b1) {
    asm volatile(
        "mma.sync.aligned.m16n8k16.row.col.f32.bf16.bf16.f32 "
        "{%0,%1,%2,%3}, {%4,%5,%6,%7}, {%8,%9}, {%0,%1,%2,%3};"
        : "+f"(c0), "+f"(c1), "+f"(c2), "+f"(c3)
        : "r"(a0), "r"(a1), "r"(a2), "r"(a3), "r"(b0), "r"(b1));
}

__device__ __forceinline__ void k1_issue_slice(const float* __restrict__ H,
                                               const float* __restrict__ X,
                                               int n0s, int t0, int buf,
                                               uint32_t smb, int tid) {
    const uint32_t stH = smb + (uint32_t)((buf * 2 + 0) * STG_MAT) * 4u;
    const uint32_t stX = smb + (uint32_t)((buf * 2 + 1) * STG_MAT) * 4u;
#pragma unroll
    for (int i = 0; i < 4; i++) {
        int ch = tid + i * 512;          // 0..2047
        int r = ch >> 5;                 // staging row 0..63
        int j = ch & 31;                 // 16B chunk within row
        int js = j ^ ((r >> 1) & 7);     // swizzle (low 3 bits)
        uint32_t doff = (uint32_t)(r * 512 + js * 16);
        int n = n0s + r;
        if (n < N_NODES) {
            const float* gH = H + (size_t)n * T_SEQ + t0 + j * 4;
            const float* gX = X + (size_t)n * IN_CH + j * 4;
            asm volatile("cp.async.ca.shared.global [%0], [%1], 16;"
                         :: "r"(stH + doff), "l"(gH));
            asm volatile("cp.async.ca.shared.global [%0], [%1], 16;"
                         :: "r"(stX + doff), "l"(gX));
        } else {
            asm volatile("st.shared.v4.u32 [%0], {%1,%1,%1,%1};"
                         :: "r"(stH + doff), "r"(0u) : "memory");
            asm volatile("st.shared.v4.u32 [%0], {%1,%1,%1,%1};"
                         :: "r"(stX + doff), "r"(0u) : "memory");
        }
    }
}

__global__ void __launch_bounds__(512, 1) k1h_kernel(const float* __restrict__ H,
                                                     const float* __restrict__ X) {
    extern __shared__ uint32_t smw[];
    float* stf = (float*)smw;
    uint32_t smb;
    asm("{ .reg .u64 t; cvta.to.shared.u64 t, %1; cvt.u32.u64 %0, t; }"
        : "=r"(smb) : "l"((const void*)smw));

    const int tid = threadIdx.x;
    const int t0 = blockIdx.x * 128;
    const int n0 = blockIdx.y * K1_CHUNK;

    const int kp = tid & 31;
    const int mg = tid >> 5;
    const int kx = kp & 7;

    const int wid = tid >> 5, lane = tid & 31;
    const int wm = wid >> 2, wn = wid & 3;
    const int lr = lane >> 2, lc = lane & 3;

    float c[2][4][4];
#pragma unroll
    for (int mt = 0; mt < 2; mt++)
#pragma unroll
        for (int nt = 0; nt < 4; nt++)
#pragma unroll
            for (int r = 0; r < 4; r++) c[mt][nt][r] = 0.f;

    k1_issue_slice(H, X, n0, t0, 0, smb, tid);
    asm volatile("cp.async.commit_group;" ::: "memory");

    for (int s = 0; s < NSLICES; s++) {
        const int buf = s & 1;

        if (s + 1 < NSLICES) {
            k1_issue_slice(H, X, n0 + (s + 1) * 64, t0, buf ^ 1, smb, tid);
            asm volatile("cp.async.commit_group;" ::: "memory");
            asm volatile("cp.async.wait_group 1;" ::: "memory");
        } else {
            asm volatile("cp.async.wait_group 0;" ::: "memory");
        }
        __syncthreads();   // staging[buf] visible to all

#pragma unroll
        for (int tsel = 0; tsel < 2; tsel++) {
            const int so = (buf * 2 + tsel) * STG_MAT;
            const int offh = tsel ? OFF_BH : OFF_AH;
            const int offl = tsel ? OFF_BL : OFF_AL;
            const float* r0p = stf + so + (2 * kp) * STG_ROW;
            const float* r1p = stf + so + (2 * kp + 1) * STG_ROW;
            float4 v00 = *(const float4*)(r0p + (((2 * mg)     ^ kx) << 2));
            float4 v01 = *(const float4*)(r0p + (((2 * mg + 1) ^ kx) << 2));
            float4 v10 = *(const float4*)(r1p + (((2 * mg)     ^ kx) << 2));
            float4 v11 = *(const float4*)(r1p + (((2 * mg + 1) ^ kx) << 2));
            const float* e0 = &v00.x;
            const float* f0 = &v01.x;
            const float* e1 = &v10.x;
            const float* f1 = &v11.x;
#pragma unroll
            for (int j = 0; j < 8; j++) {
                float v0 = (j < 4) ? e0[j] : f0[j - 4];
                float v1 = (j < 4) ? e1[j] : f1[j - 4];
                __nv_bfloat162 hi2 = __floats2bfloat162_rn(v0, v1);
                float l0 = v0 - __bfloat162float(hi2.x);
                float l1 = v1 - __bfloat162float(hi2.y);
                __nv_bfloat162 lo2 = __floats2bfloat162_rn(l0, l1);
                int m = mg * 8 + j;
                smw[offh + m * WSTR + kp] = *(uint32_t*)&hi2;
                smw[offl + m * WSTR + kp] = *(uint32_t*)&lo2;
            }
        }

        __syncthreads();   // tiles visible

#pragma unroll
        for (int ks = 0; ks < 4; ks++) {
            const int ksw = ks * 8;
            uint32_t ah[2][4], al[2][4], bh[4][2], bl[4][2];
#pragma unroll
            for (int mt = 0; mt < 2; mt++) {
                int row = wm * 32 + mt * 16 + lr;
                const uint32_t* pa = smw + row * WSTR + ksw + lc;
                ah[mt][0] = pa[OFF_AH];
                ah[mt][1] = pa[OFF_AH + 8 * WSTR];
                ah[mt][2] = pa[OFF_AH + 4];
                ah[mt][3] = pa[OFF_AH + 8 * WSTR + 4];
                al[mt][0] = pa[OFF_AL];
                al[mt][1] = pa[OFF_AL + 8 * WSTR];
                al[mt][2] = pa[OFF_AL + 4];
                al[mt][3] = pa[OFF_AL + 8 * WSTR + 4];
            }
#pragma unroll
            for (int nt = 0; nt < 4; nt++) {
                int nrow = wn * 32 + nt * 8 + lr;
                const uint32_t* pb = smw + nrow * WSTR + ksw + lc;
                bh[nt][0] = pb[OFF_BH];
                bh[nt][1] = pb[OFF_BH + 4];
                bl[nt][0] = pb[OFF_BL];
                bl[nt][1] = pb[OFF_BL + 4];
            }
#pragma unroll
            for (int mt = 0; mt < 2; mt++)
#pragma unroll
                for (int nt = 0; nt < 4; nt++) {
                    float* cc = c[mt][nt];
                    mma_bf16(cc[0], cc[1], cc[2], cc[3],
                             ah[mt][0], ah[mt][1], ah[mt][2], ah[mt][3],
                             bh[nt][0], bh[nt][1]);
                    mma_bf16(cc[0], cc[1], cc[2], cc[3],
                             ah[mt][0], ah[mt][1], ah[mt][2], ah[mt][3],
                             bl[nt][0], bl[nt][1]);
                    mma_bf16(cc[0], cc[1], cc[2], cc[3],
                             al[mt][0], al[mt][1], al[mt][2], al[mt][3],
                             bh[nt][0], bh[nt][1]);
                }
        }

        __syncthreads();   // MMA reads done before next slice's stores
    }

    float* pp = g_part + (size_t)blockIdx.y * (T_SEQ * IN_CH);
#pragma unroll
    for (int mt = 0; mt < 2; mt++) {
#pragma unroll
        for (int nt = 0; nt < 4; nt++) {
            int row0 = wm * 32 + mt * 16 + lr;
            int col = wn * 32 + nt * 8 + lc * 2;
            *(float2*)(pp + (size_t)(t0 + row0) * IN_CH + col) =
                make_float2(c[mt][nt][0], c[mt][nt][1]);
            *(float2*)(pp + (size_t)(t0 + row0 + 8) * IN_CH + col) =
                make_float2(c[mt][nt][2], c[mt][nt][3]);
        }
    }
}

// K1b: ve = sum over 37 chunk partials (deterministic reduce)
__global__ void __launch_bounds__(256) k1_reduce_kernel() {
    int idx = blockIdx.x * blockDim.x + threadIdx.x;   // 0..131071
    float s = 0.f;
#pragma unroll
    for (int c = 0; c < K1_NCHUNK; c++) s += g_part[c * (T_SEQ * IN_CH) + idx];
    g_ve[idx] = s;
}

// ============================================================================
// K2: gx[t][r] = b_ih[r] + sum_k ve[t][k]*w_ih[r][k]
// ============================================================================
__global__ void __launch_bounds__(256) gx_kernel(const float* __restrict__ w_ih,
                                                 const float* __restrict__ b_ih) {
    const int t = blockIdx.x;
    const int w = threadIdx.x >> 5, l = threadIdx.x & 31;
    float4 vv = *(const float4*)(g_ve + t * IN_CH + l * 4);
    for (int rr = 0; rr < 96; rr++) {
        int r = w * 96 + rr;
        float4 wv = *(const float4*)(w_ih + (size_t)r * IN_CH + l * 4);
        float p = vv.x * wv.x + vv.y * wv.y + vv.z * wv.z + vv.w * wv.w;
#pragma unroll
        for (int o = 16; o; o >>= 1) p += __shfl_xor_sync(0xffffffffu, p, o);
        if (l == 0) g_gx[t * G3 + r] = p + b_ih[r];
    }
}

// ============================================================================
// K3: sequential GRU, 16-CTA cluster x 128 threads.
// Handshake v4: hnew staged to SMEM (16 floats = 64B per CTA), one
// __syncthreads (read-certificate + stage-complete), then 64 VECTOR sends
// per CTA: thread tid<64 sends 16B (st.async.v4) chunk tid&3 to peer tid>>2.
// Destination barrier processes 64 incoming tx/step instead of 512 (the
// round-11 bottleneck). expect_tx stays 1024B.
// ============================================================================
#define GRU_NCTA 16
__device__ __forceinline__ void cluster_sync_() {
    asm volatile("barrier.cluster.arrive.aligned;" ::: "memory");
    asm volatile("barrier.cluster.wait.aligned;" ::: "memory");
}
__device__ __forceinline__ void st_async_v4(uint32_t laddr, uint32_t lbar,
                                            uint32_t peer, float4 v) {
    uint32_t ra, rb;
    asm volatile("mapa.shared::cluster.u32 %0, %1, %2;"
                 : "=r"(ra) : "r"(laddr), "r"(peer));
    asm volatile("mapa.shared::cluster.u32 %0, %1, %2;"
                 : "=r"(rb) : "r"(lbar), "r"(peer));
    asm volatile(
        "st.async.shared::cluster.mbarrier::complete_tx::bytes.v4.b32 "
        "[%0], {%1,%2,%3,%4}, [%5];"
        :: "r"(ra), "r"(__float_as_uint(v.x)), "r"(__float_as_uint(v.y)),
           "r"(__float_as_uint(v.z)), "r"(__float_as_uint(v.w)), "r"(rb)
        : "memory");
}
__device__ __forceinline__ void arm_expect_tx(uint32_t bar, uint32_t bytes) {
    asm volatile("mbarrier.arrive.expect_tx.shared.b64 _, [%0], %1;"
                 :: "r"(bar), "r"(bytes) : "memory");
}
__device__ __forceinline__ void wait_parity_cl(uint32_t bar, uint32_t par) {
    uint32_t done;
    do {
        asm volatile(
            "{\n\t.reg .pred p;\n\t"
            "mbarrier.try_wait.parity.acquire.cluster.shared::cta.b64 p, [%1], %2, 0x989680;\n\t"
            "selp.b32 %0, 1, 0, p;\n\t}"
            : "=r"(done) : "r"(bar), "r"(par) : "memory");
    } while (!done);
}
__device__ __forceinline__ float tanh_ap(float x) {
    float y;
    asm("tanh.approx.f32 %0, %1;" : "=f"(y) : "f"(x));
    return y;
}
__device__ __forceinline__ float sigmoid_ap(float x) {
    return fmaf(0.5f, tanh_ap(0.5f * x), 0.5f);
}

__global__ void __launch_bounds__(128, 1)
gru_kernel(const float* __restrict__ w_hh, const float* __restrict__ b_hh) {
    __shared__ __align__(16) float sh_h[2][256];            // double-buffered h
    __shared__ __align__(16) float sh_stage[16];            // this CTA's hnew
    __shared__ __align__(8) unsigned long long sh_bar[2];   // full barrier per buf

    const int tid = threadIdx.x;
    const int rank = blockIdx.x;       // 0..15
    const int j = tid >> 3;            // slot 0..15
    const int o = tid & 7;             // k-octant 0..7
    const int slot = rank * 16 + j;    // global h index owned by this group

    unsigned long long wr[16], wz[16], wn[16];
#pragma unroll
    for (int i = 0; i < 16; i++) {
        int k = o * 32 + ((i + 2 * o) & 15) * 2;
        wr[i] = *(const unsigned long long*)(w_hh + (size_t)(slot)*256 + k);
        wz[i] = *(const unsigned long long*)(w_hh + (size_t)(256 + slot) * 256 + k);
        wn[i] = *(const unsigned long long*)(w_hh + (size_t)(512 + slot) * 256 + k);
    }
    const float bhr = b_hh[slot];
    const float bhz = b_hh[256 + slot];
    const float bhn = b_hh[512 + slot];

    sh_h[0][tid] = 0.f;   sh_h[0][tid + 128] = 0.f;
    sh_h[1][tid] = 0.f;   sh_h[1][tid + 128] = 0.f;
    uint32_t bbase = (uint32_t)__cvta_generic_to_shared(&sh_bar[0]);
    if (tid == 0) {
        asm volatile("mbarrier.init.shared.b64 [%0], %1;" :: "r"(bbase),     "r"(1) : "memory");
        asm volatile("mbarrier.init.shared.b64 [%0], %1;" :: "r"(bbase + 8), "r"(1) : "memory");
        arm_expect_tx(bbase, 1024u);       // buffer-0 stores (written at step 1)
        arm_expect_tx(bbase + 8, 1024u);   // buffer-1 stores (written at step 0)
    }
    __syncthreads();
    cluster_sync_();   // barriers + h0 visible cluster-wide

    for (int t = 0; t < T_SEQ; t++) {
        const int cur = t & 1, nxt = cur ^ 1;

        // gx loads (h-independent) issued before the wait to hide latency
        const float gxr = g_gx[t * G3 + slot];
        const float gxz = g_gx[t * G3 + 256 + slot];
        const float gxn = g_gx[t * G3 + 512 + slot];

        if (t > 0) {
            wait_parity_cl(bbase + 8u * (uint32_t)cur, ((t - 1) >> 1) & 1);
            if (tid == 0) arm_expect_tx(bbase + 8u * (uint32_t)cur, 1024u);
        }

        const float hprev = sh_h[cur][slot];

        unsigned long long ar = 0ull, az = 0ull, an = 0ull;
        {
            const float* hb = &sh_h[cur][0];
#pragma unroll
            for (int i = 0; i < 16; i++) {
                int k = o * 32 + ((i + 2 * o) & 15) * 2;
                unsigned long long hv = *(const unsigned long long*)(hb + k);
                asm("fma.rn.f32x2 %0, %1, %2, %0;" : "+l"(ar) : "l"(wr[i]), "l"(hv));
                asm("fma.rn.f32x2 %0, %1, %2, %0;" : "+l"(az) : "l"(wz[i]), "l"(hv));
                asm("fma.rn.f32x2 %0, %1, %2, %0;" : "+l"(an) : "l"(wn[i]), "l"(hv));
            }
        }
        float pr, pz, pn;
        {
            float lo, hi;
            asm("mov.b64 {%0, %1}, %2;" : "=f"(lo), "=f"(hi) : "l"(ar)); pr = lo + hi;
            asm("mov.b64 {%0, %1}, %2;" : "=f"(lo), "=f"(hi) : "l"(az)); pz = lo + hi;
            asm("mov.b64 {%0, %1}, %2;" : "=f"(lo), "=f"(hi) : "l"(an)); pn = lo + hi;
        }
#pragma unroll
        for (int d = 1; d < 8; d <<= 1) {
            pr += __shfl_xor_sync(0xffffffffu, pr, d);
            pz += __shfl_xor_sync(0xffffffffu, pz, d);
            pn += __shfl_xor_sync(0xffffffffu, pn, d);
        }

        const float r = sigmoid_ap(gxr + pr + bhr);
        const float z = sigmoid_ap(gxz + pz + bhz);
        const float n = tanh_ap(gxn + r * (pn + bhn));
        const float hnew = n + z * (hprev - n);

        if (o == 0) {
            sh_stage[j] = hnew;
            g_hs[t * HID + slot] = hnew;
        }

        if (t < T_SEQ - 1) {
            // certifies: all reads of sh_h[cur] retired AND sh_stage complete
            __syncthreads();
            if (tid < 64) {
                const int peer = tid >> 2;       // 0..15 (incl. self)
                const int chunk = tid & 3;       // 0..3 (4 slots each)
                float4 v = *(const float4*)&sh_stage[chunk * 4];
                uint32_t laddr = (uint32_t)__cvta_generic_to_shared(
                    &sh_h[nxt][rank * 16 + chunk * 4]);
                st_async_v4(laddr, bbase + 8u * (uint32_t)nxt, (uint32_t)peer, v);
            }
        }
    }
    cluster_sync_();   // drain in-flight traffic before exit
}

// ============================================================================
// K4: logits = hs @ w_attn; alpha = softmax(logits); out = alpha @ hs
// ============================================================================
__global__ void __launch_bounds__(1024) attn_kernel(const float* __restrict__ w_attn,
                                                    float* __restrict__ out) {
    __shared__ float s_alpha[1024];
    __shared__ float s_red[1024];
    __shared__ float s_wa[256];
    const int tid = threadIdx.x;
    if (tid < 256) s_wa[tid] = w_attn[tid];
    __syncthreads();

    const int w = tid >> 5, l = tid & 31;
    for (int tt = 0; tt < 32; tt++) {
        int t = w * 32 + tt;
        const float* hr = g_hs + t * HID;
        float p = 0.f;
#pragma unroll
        for (int j = 0; j < 8; j++) p = fmaf(hr[l + 32 * j], s_wa[l + 32 * j], p);
#pragma unroll
        for (int o = 16; o; o >>= 1) p += __shfl_xor_sync(0xffffffffu, p, o);
        if (l == 0) s_alpha[t] = p;
    }
    __syncthreads();

    float v = s_alpha[tid];
    s_red[tid] = v;
    __syncthreads();
    for (int s = 512; s; s >>= 1) {
        if (tid < s) s_red[tid] = fmaxf(s_red[tid], s_red[tid + s]);
        __syncthreads();
    }
    float m = s_red[0];
    __syncthreads();
    float e = __expf(v - m);
    s_red[tid] = e;
    __syncthreads();
    for (int s = 512; s; s >>= 1) {
        if (tid < s) s_red[tid] = s_red[tid] + s_red[tid + s];
        __syncthreads();
    }
    float inv = 1.f / s_red[0];
    __syncthreads();
    s_alpha[tid] = e * inv;
    __syncthreads();

    const int j = tid & 255, seg = tid >> 8;
    float p = 0.f;
    const float* hp = g_hs + (size_t)seg * 256 * HID + j;
    const float* ap = s_alpha + seg * 256;
    for (int t = 0; t < 256; t++) p = fmaf(ap[t], hp[t * HID], p);
    s_red[tid] = p;
    __syncthreads();
    if (tid < 256)
        out[j] = (s_red[j] + s_red[256 + j]) + (s_red[512 + j] + s_red[768 + j]);
}

// ============================================================================
extern "C" void kernel_launch(void* const* d_in, const int* in_sizes, int n_in,
                              void* d_out, int out_size) {
    const float* X = nullptr;
    const float* H = nullptr;
    const float* w_ih = nullptr;
    const float* w_hh = nullptr;
    const float* b_ih = nullptr;
    const float* b_hh = nullptr;
    const float* w_attn = nullptr;
    for (int i = 0; i < n_in; i++) {
        int s = in_sizes[i];
        const float* p = (const float*)d_in[i];
        if (s == N_NODES * IN_CH)      X = p;
        else if (s == N_NODES * T_SEQ) H = p;
        else if (s == G3 * IN_CH)      w_ih = p;
        else if (s == G3 * HID)        w_hh = p;
        else if (s == G3) { if (!b_ih) b_ih = p; else b_hh = p; }
        else if (s == HID)             w_attn = p;
    }
    float* out = (float*)d_out;

    cudaFuncSetAttribute(k1h_kernel, cudaFuncAttributeMaxDynamicSharedMemorySize,
                         K1_SMEM_BYTES);

    k1h_kernel<<<dim3(8, K1_NCHUNK), 512, K1_SMEM_BYTES>>>(H, X);
    k1_reduce_kernel<<<(T_SEQ * IN_CH) / 256, 256>>>();
    gx_kernel<<<T_SEQ, 256>>>(w_ih, b_ih);

    // GRU: 16-CTA cluster (non-portable size), runtime cluster attribute
    cudaFuncSetAttribute(gru_kernel,
                         cudaFuncAttributeNonPortableClusterSizeAllowed, 1);
    {
        cudaLaunchConfig_t cfg = {};
        cfg.gridDim = dim3(GRU_NCTA, 1, 1);
        cfg.blockDim = dim3(128, 1, 1);
        cfg.dynamicSmemBytes = 0;
        cudaLaunchAttribute attrs[1];
        attrs[0].id = cudaLaunchAttributeClusterDimension;
        attrs[0].val.clusterDim = {GRU_NCTA, 1, 1};
        cfg.attrs = attrs;
        cfg.numAttrs = 1;
        cudaLaunchKernelEx(&cfg, gru_kernel, w_hh, b_hh);
    }

    attn_kernel<<<1, 1024>>>(w_attn, out);
}